// round 4
// baseline (speedup 1.0000x reference)
#include <cuda_runtime.h>
#include <cuda_bf16.h>
#include <math.h>

// Problem dims
#define BB 32
#define LL 100
#define CC 142
#define DM 512
#define DI 1024
#define NS 16
#define KC 4
#define DTR 32
#define NL 6
#define OD 128
#define MROWS (BB*LL)   // 3200
#define CPAD 144        // 142 padded to multiple of 16

#define STAGES 3
#define SROW 20                      // padded row stride (floats) -> conflict-free
#define TILE_F (128*SROW)            // floats per tile per stage
#define SMEM_BYTES (STAGES*2*TILE_F*4)

// ---------------- scratch (device globals; no allocation allowed) ----------------
__device__ __align__(16) float g_h   [MROWS*DM];
__device__ __align__(16) float g_hn  [MROWS*DM];
__device__ __align__(16) float g_xz  [MROWS*2*DI];
__device__ __align__(16) float g_xc  [MROWS*DI];
__device__ __align__(16) float g_xd  [MROWS*64];
__device__ __align__(16) float g_xsp [4*MROWS*64];
__device__ __align__(16) float g_dt  [MROWS*DI];
__device__ __align__(16) float g_yg  [MROWS*DI];
__device__ __align__(16) float g_xpad[MROWS*CPAD];
__device__ __align__(16) float g_wpad[DM*CPAD];
__device__ __align__(16) float g_last[BB*DM];
__device__ __align__(16) float g_hid [BB*DM];

// ---------------- padding for the embed GEMM (K=142 -> 144) ----------------
__global__ void pad_kernel(const float* __restrict__ x, const float* __restrict__ w)
{
    int i = blockIdx.x * 256 + threadIdx.x;
    if (i < MROWS*CPAD) {
        int m = i / CPAD, c = i % CPAD;
        g_xpad[i] = (c < CC) ? x[m*CC + c] : 0.f;
    }
    int j = i - MROWS*CPAD;
    if (j >= 0 && j < DM*CPAD) {
        int m = j / CPAD, c = j % CPAD;
        g_wpad[j] = (c < CC) ? w[m*CC + c] : 0.f;
    }
}

// ---------------- mma + cp.async helpers ----------------
__device__ __forceinline__ void mma_tf32(float* c, const unsigned* a, const unsigned* b)
{
    asm volatile(
        "mma.sync.aligned.m16n8k8.row.col.f32.tf32.tf32.f32 "
        "{%0,%1,%2,%3}, {%4,%5,%6,%7}, {%8,%9}, {%0,%1,%2,%3};"
        : "+f"(c[0]), "+f"(c[1]), "+f"(c[2]), "+f"(c[3])
        : "r"(a[0]), "r"(a[1]), "r"(a[2]), "r"(a[3]),
          "r"(b[0]), "r"(b[1]));
}

__device__ __forceinline__ void cp16(unsigned dst, const float* src)
{
    asm volatile("cp.async.cg.shared.global [%0], [%1], 16;\n" :: "r"(dst), "l"(src));
}
__device__ __forceinline__ void cp_commit() { asm volatile("cp.async.commit_group;\n"); }
template<int N>
__device__ __forceinline__ void cp_wait() { asm volatile("cp.async.wait_group %0;\n" :: "n"(N)); }

// ---------------- TF32 tensor-core GEMM, cp.async 3-stage pipeline ----------------
// C[M,N] = A[M,K] * W[N,K]^T (+epilogue). 128x128 tile, BK=16, 256 thr = 8 warps (2x4),
// warp tile 64x32. Smem tiles row-major [128][20] (pad->conflict-free scalar LDS).
// fp32 bits fed to tf32 mma directly (HW truncates mantissa).
// blockIdx.z = split-K slice: A/W column offset z*Kk, C offset z*cOff.
// EPI: 0 = store, 1 = +bias +pos(row%LL), 2 = C += acc, 3 = softplus(acc+bias)
template<int EPI>
__global__ void __launch_bounds__(256) gemm_tc(
    const float* __restrict__ A, int lda,
    const float* __restrict__ W, int ldw,
    float* __restrict__ C, int ldc,
    int Nn, int Kk, int cOff,
    const float* __restrict__ bias,
    const float* __restrict__ pos)
{
    extern __shared__ __align__(16) float smem[];
    float* Asm = smem;                    // [STAGES][TILE_F]
    float* Bsm = smem + STAGES*TILE_F;

    const int m0  = blockIdx.y * 128;
    const int n0  = blockIdx.x * 128;
    const int z   = blockIdx.z;
    const int tid = threadIdx.x;
    const int lane = tid & 31;
    const int wid  = tid >> 5;
    const int warp_m = wid & 1;    // 0..1 -> 64 rows
    const int warp_n = wid >> 1;   // 0..3 -> 32 cols
    const int zoff = z * Kk;

    // loader: 16B chunks, ids tid / tid+256 ; id -> row=id>>2, kc=(id&3)*4
    const int r0 = tid >> 2,         kc0 = (tid & 3) * 4;
    const int r1 = (tid + 256) >> 2, kc1 = ((tid + 256) & 3) * 4;

    const float* A0 = A + (size_t)(m0 + r0) * lda + zoff + kc0;
    const float* A1 = A + (size_t)(m0 + r1) * lda + zoff + kc1;
    const int w0r = (n0 + r0 < Nn) ? (n0 + r0) : 0;
    const int w1r = (n0 + r1 < Nn) ? (n0 + r1) : 0;
    const float* W0 = W + (size_t)w0r * ldw + zoff + kc0;
    const float* W1 = W + (size_t)w1r * ldw + zoff + kc1;

    unsigned sA0 = (unsigned)__cvta_generic_to_shared(Asm + r0*SROW + kc0);
    unsigned sA1 = (unsigned)__cvta_generic_to_shared(Asm + r1*SROW + kc1);
    unsigned sB0 = (unsigned)__cvta_generic_to_shared(Bsm + r0*SROW + kc0);
    unsigned sB1 = (unsigned)__cvta_generic_to_shared(Bsm + r1*SROW + kc1);

    const int iters = Kk >> 4;

    // prologue: issue first STAGES-1 k-blocks
    #pragma unroll
    for (int s = 0; s < STAGES-1; s++) {
        if (s < iters) {
            int ko = s << 4;
            unsigned so = s * TILE_F * 4;
            cp16(sA0 + so, A0 + ko);
            cp16(sA1 + so, A1 + ko);
            cp16(sB0 + so, W0 + ko);
            cp16(sB1 + so, W1 + ko);
        }
        cp_commit();
    }

    float acc[4][4][4];
    #pragma unroll
    for (int i = 0; i < 4; i++)
        #pragma unroll
        for (int j = 0; j < 4; j++)
            #pragma unroll
            for (int r = 0; r < 4; r++) acc[i][j][r] = 0.f;

    const int lane_off = (lane >> 2) * SROW + (lane & 3);

    int stg = 0;
    for (int it = 0; it < iters; it++) {
        cp_wait<STAGES-2>();
        __syncthreads();

        // issue k-block it+STAGES-1 into the stage just freed
        {
            int nit = it + STAGES - 1;
            if (nit < iters) {
                int ko = nit << 4;
                int ns = stg + STAGES - 1; if (ns >= STAGES) ns -= STAGES;
                unsigned so = ns * TILE_F * 4;
                cp16(sA0 + so, A0 + ko);
                cp16(sA1 + so, A1 + ko);
                cp16(sB0 + so, W0 + ko);
                cp16(sB1 + so, W1 + ko);
            }
            cp_commit();
        }

        const unsigned* as = (const unsigned*)(Asm + stg*TILE_F) + warp_m*64*SROW + lane_off;
        const unsigned* bs = (const unsigned*)(Bsm + stg*TILE_F) + warp_n*32*SROW + lane_off;

        #pragma unroll
        for (int ks = 0; ks < 2; ks++) {
            const int k0 = ks * 8;
            unsigned afr[4][4], bfr[4][2];
            #pragma unroll
            for (int mt = 0; mt < 4; mt++) {
                const unsigned* p = as + mt*16*SROW + k0;
                afr[mt][0] = p[0];
                afr[mt][1] = p[8*SROW];
                afr[mt][2] = p[4];
                afr[mt][3] = p[8*SROW + 4];
            }
            #pragma unroll
            for (int nt = 0; nt < 4; nt++) {
                const unsigned* p = bs + nt*8*SROW + k0;
                bfr[nt][0] = p[0];
                bfr[nt][1] = p[4];
            }
            #pragma unroll
            for (int mt = 0; mt < 4; mt++)
                #pragma unroll
                for (int nt = 0; nt < 4; nt++)
                    mma_tf32(acc[mt][nt], afr[mt], bfr[nt]);
        }

        stg++; if (stg >= STAGES) stg = 0;
    }

    // epilogue
    float* Cz = C + (size_t)z * cOff;
    #pragma unroll
    for (int mt = 0; mt < 4; mt++) {
        #pragma unroll
        for (int rr = 0; rr < 2; rr++) {    // rows +0 / +8
            int r = m0 + warp_m*64 + mt*16 + (lane >> 2) + rr*8;
            #pragma unroll
            for (int nt = 0; nt < 4; nt++) {
                int c = n0 + warp_n*32 + nt*8 + (lane & 3)*2;
                if (c >= Nn) continue;
                float v0 = acc[mt][nt][rr*2 + 0];
                float v1 = acc[mt][nt][rr*2 + 1];
                size_t o = (size_t)r * ldc + c;
                if (EPI == 0) {
                    Cz[o]   = v0;
                    Cz[o+1] = v1;
                } else if (EPI == 1) {
                    const float* pr = pos + (size_t)(r % LL) * DM;
                    Cz[o]   = v0 + bias[c]   + pr[c];
                    Cz[o+1] = v1 + bias[c+1] + pr[c+1];
                } else if (EPI == 2) {
                    Cz[o]   += v0;
                    Cz[o+1] += v1;
                } else {
                    float u0 = v0 + bias[c];
                    float u1 = v1 + bias[c+1];
                    Cz[o]   = (u0 > 20.f) ? u0 : log1pf(__expf(u0));
                    Cz[o+1] = (u1 > 20.f) ? u1 : log1pf(__expf(u1));
                }
            }
        }
    }
}

// ---------------- reduce 4 split-K slices of xproj into g_xd ----------------
__global__ void reduce4_kernel()
{
    int i = blockIdx.x * 256 + threadIdx.x;
    if (i < MROWS*64) {
        const int S = MROWS*64;
        g_xd[i] = (g_xsp[i] + g_xsp[i + S]) + (g_xsp[i + 2*S] + g_xsp[i + 3*S]);
    }
}

// ---------------- LayerNorm over DM=512 ----------------
__global__ void ln_kernel(const float* __restrict__ in, float* __restrict__ out,
                          const float* __restrict__ g, const float* __restrict__ b,
                          int rowmul, int rowoff)
{
    int row = blockIdx.x * rowmul + rowoff;
    const float* x = in + (size_t)row * DM;
    int tid = threadIdx.x; // 256
    float v0 = x[tid], v1 = x[tid + 256];
    float s  = v0 + v1;
    float sq = v0*v0 + v1*v1;
    #pragma unroll
    for (int o = 16; o; o >>= 1) {
        s  += __shfl_xor_sync(0xffffffffu, s,  o);
        sq += __shfl_xor_sync(0xffffffffu, sq, o);
    }
    __shared__ float ss[8], ssq[8];
    if ((tid & 31) == 0) { ss[tid>>5] = s; ssq[tid>>5] = sq; }
    __syncthreads();
    float ts = 0.f, tsq = 0.f;
    #pragma unroll
    for (int i = 0; i < 8; i++) { ts += ss[i]; tsq += ssq[i]; }
    float mean = ts * (1.f/DM);
    float var  = tsq * (1.f/DM) - mean*mean;
    float rs = rsqrtf(var + 1e-5f);
    size_t ob = (size_t)blockIdx.x * DM;
    out[ob + tid]       = (v0 - mean)*rs*g[tid]       + b[tid];
    out[ob + tid + 256] = (v1 - mean)*rs*g[tid + 256] + b[tid + 256];
}

// ---------------- depthwise causal conv (K=4) + bias + silu ----------------
__global__ void conv_kernel(const float* __restrict__ cw, const float* __restrict__ cb)
{
    int idx = blockIdx.x * 256 + threadIdx.x;
    if (idx >= MROWS*DI) return;
    int d = idx & (DI-1);
    int m = idx >> 10;
    int t = m % LL;
    float w0 = cw[d*4+0], w1 = cw[d*4+1], w2 = cw[d*4+2], w3 = cw[d*4+3];
    size_t rb = (size_t)m * (2*DI) + d;   // xp lives in cols [0,DI) of xz
    float acc = cb[d] + g_xz[rb] * w3;
    if (t >= 1) acc += g_xz[rb - 1*2*DI] * w2;
    if (t >= 2) acc += g_xz[rb - 2*2*DI] * w1;
    if (t >= 3) acc += g_xz[rb - 3*2*DI] * w0;
    float sig = 1.f / (1.f + __expf(-acc));
    g_xc[(size_t)m*DI + d] = acc * sig;
}

// ---------------- selective scan over L, fused D-skip + z-gate ----------------
__global__ void __launch_bounds__(256) scan_kernel(const float* __restrict__ A_log,
                                                   const float* __restrict__ Dp)
{
    int b   = blockIdx.y;
    int tid = threadIdx.x;
    int d   = blockIdx.x * 256 + tid;
    __shared__ float sBC[2][32];   // [buf][0..15]=B, [16..31]=C

    float hs[NS], Af[NS];
    #pragma unroll
    for (int n = 0; n < NS; n++) {
        hs[n] = 0.f;
        Af[n] = -__expf(A_log[(size_t)d*NS + n]);
    }
    float Dpd = Dp[d];
    size_t base = (size_t)b * LL;

    if (tid < 32) sBC[0][tid] = g_xd[base*64 + 32 + tid];
    __syncthreads();

    for (int t = 0; t < LL; t++) {
        int cur = t & 1;
        if (t < LL-1 && tid < 32)
            sBC[cur ^ 1][tid] = g_xd[(base + t + 1)*64 + 32 + tid];
        size_t m = base + t;
        float xcv = g_xc[m*DI + d];
        float dtv = g_dt[m*DI + d];
        float zv  = g_xz[m*2*DI + DI + d];
        float dtx = dtv * xcv;
        float acc = 0.f;
        #pragma unroll
        for (int n = 0; n < NS; n++) {
            float dA = __expf(dtv * Af[n]);
            hs[n] = fmaf(dA, hs[n], dtx * sBC[cur][n]);
            acc = fmaf(hs[n], sBC[cur][16 + n], acc);
        }
        float y = acc + Dpd * xcv;
        float sig = 1.f / (1.f + __expf(-zv));
        g_yg[m*DI + d] = y * (zv * sig);
        __syncthreads();
    }
}

// ---------------- head: gelu(last @ op1^T + b1) ----------------
__global__ void head1_kernel(const float* __restrict__ w, const float* __restrict__ bias)
{
    int b = blockIdx.x;
    int j = threadIdx.x; // 512
    __shared__ float xr[DM];
    xr[j] = g_last[(size_t)b*DM + j];
    __syncthreads();
    const float4* wr = (const float4*)(w + (size_t)j*DM);
    float s = bias[j];
    #pragma unroll 4
    for (int k = 0; k < DM/4; k++) {
        float4 wv = wr[k];
        const float* xv = &xr[k*4];
        s = fmaf(wv.x, xv[0], s);
        s = fmaf(wv.y, xv[1], s);
        s = fmaf(wv.z, xv[2], s);
        s = fmaf(wv.w, xv[3], s);
    }
    g_hid[(size_t)b*DM + j] = 0.5f * s * (1.f + erff(s * 0.70710678118654752f));
}

// ---------------- head: hid @ op2^T + b2 -> output ----------------
__global__ void head2_kernel(const float* __restrict__ w, const float* __restrict__ bias,
                             float* __restrict__ out)
{
    int b = blockIdx.x;
    int o = threadIdx.x; // 128
    __shared__ float xr[DM];
    for (int k = o; k < DM; k += 128) xr[k] = g_hid[(size_t)b*DM + k];
    __syncthreads();
    const float4* wr = (const float4*)(w + (size_t)o*DM);
    float s = bias[o];
    #pragma unroll 4
    for (int k = 0; k < DM/4; k++) {
        float4 wv = wr[k];
        const float* xv = &xr[k*4];
        s = fmaf(wv.x, xv[0], s);
        s = fmaf(wv.y, xv[1], s);
        s = fmaf(wv.z, xv[2], s);
        s = fmaf(wv.w, xv[3], s);
    }
    out[(size_t)b*OD + o] = s;
}

// ---------------- launch ----------------
extern "C" void kernel_launch(void* const* d_in, const int* in_sizes, int n_in,
                              void* d_out, int out_size)
{
    const float* x      = (const float*)d_in[0];
    const float* inp_w  = (const float*)d_in[1];
    const float* inp_b  = (const float*)d_in[2];
    const float* pos    = (const float*)d_in[3];
    const float* norm_g = (const float*)d_in[4];
    const float* norm_b = (const float*)d_in[5];
    const float* in_w   = (const float*)d_in[6];
    const float* conv_w = (const float*)d_in[7];
    const float* conv_b = (const float*)d_in[8];
    const float* xproj_w= (const float*)d_in[9];
    const float* dt_w   = (const float*)d_in[10];
    const float* dt_b   = (const float*)d_in[11];
    const float* A_log  = (const float*)d_in[12];
    const float* Dp     = (const float*)d_in[13];
    const float* out_w  = (const float*)d_in[14];
    const float* lnf_g  = (const float*)d_in[15];
    const float* lnf_b  = (const float*)d_in[16];
    const float* op1_w  = (const float*)d_in[17];
    const float* op1_b  = (const float*)d_in[18];
    const float* op2_w  = (const float*)d_in[19];
    const float* op2_b  = (const float*)d_in[20];
    float* outp = (float*)d_out;

    float *p_h, *p_hn, *p_xz, *p_xc, *p_xd, *p_xsp, *p_dt, *p_yg, *p_xpad, *p_wpad;
    cudaGetSymbolAddress((void**)&p_h,    g_h);
    cudaGetSymbolAddress((void**)&p_hn,   g_hn);
    cudaGetSymbolAddress((void**)&p_xz,   g_xz);
    cudaGetSymbolAddress((void**)&p_xc,   g_xc);
    cudaGetSymbolAddress((void**)&p_xd,   g_xd);
    cudaGetSymbolAddress((void**)&p_xsp,  g_xsp);
    cudaGetSymbolAddress((void**)&p_dt,   g_dt);
    cudaGetSymbolAddress((void**)&p_yg,   g_yg);
    cudaGetSymbolAddress((void**)&p_xpad, g_xpad);
    cudaGetSymbolAddress((void**)&p_wpad, g_wpad);
    float *p_last, *p_hid;
    cudaGetSymbolAddress((void**)&p_last, g_last);
    cudaGetSymbolAddress((void**)&p_hid,  g_hid);

    // allow >48KB dynamic smem for the pipelined GEMM
    cudaFuncSetAttribute(gemm_tc<0>, cudaFuncAttributeMaxDynamicSharedMemorySize, SMEM_BYTES);
    cudaFuncSetAttribute(gemm_tc<1>, cudaFuncAttributeMaxDynamicSharedMemorySize, SMEM_BYTES);
    cudaFuncSetAttribute(gemm_tc<2>, cudaFuncAttributeMaxDynamicSharedMemorySize, SMEM_BYTES);
    cudaFuncSetAttribute(gemm_tc<3>, cudaFuncAttributeMaxDynamicSharedMemorySize, SMEM_BYTES);

    // 1) pad x / inp_w, then embed GEMM (+bias +pos), K=144
    {
        int total = MROWS*CPAD + DM*CPAD;
        pad_kernel<<<(total + 255)/256, 256>>>(x, inp_w);
        dim3 g(DM/128, MROWS/128);
        gemm_tc<1><<<g, 256, SMEM_BYTES>>>(p_xpad, CPAD, p_wpad, CPAD, p_h, DM, DM, CPAD, 0, inp_b, pos);
    }

    // 2) layers
    for (int i = 0; i < NL; i++) {
        ln_kernel<<<MROWS, 256>>>(p_h, p_hn, norm_g + i*DM, norm_b + i*DM, 1, 0);

        dim3 g1(2*DI/128, MROWS/128);
        gemm_tc<0><<<g1, 256, SMEM_BYTES>>>(p_hn, DM, in_w + (size_t)i*2*DI*DM, DM,
                                p_xz, 2*DI, 2*DI, DM, 0, nullptr, nullptr);

        conv_kernel<<<(MROWS*DI + 255)/256, 256>>>(conv_w + (size_t)i*DI*KC, conv_b + (size_t)i*DI);

        // xproj: split-K x4 (K=1024 -> 4 slices of 256) into g_xsp, then reduce
        dim3 g2(1, MROWS/128, 4);
        gemm_tc<0><<<g2, 256, SMEM_BYTES>>>(p_xc, DI, xproj_w + (size_t)i*64*DI, DI,
                                p_xsp, 64, 64, DI/4, MROWS*64, nullptr, nullptr);
        reduce4_kernel<<<(MROWS*64 + 255)/256, 256>>>();

        dim3 g3(DI/128, MROWS/128);
        gemm_tc<3><<<g3, 256, SMEM_BYTES>>>(p_xd, 64, dt_w + (size_t)i*DI*DTR, DTR,
                                p_dt, DI, DI, DTR, 0, dt_b + (size_t)i*DI, nullptr);

        dim3 gs(DI/256, BB);
        scan_kernel<<<gs, 256>>>(A_log + (size_t)i*DI*NS, Dp + (size_t)i*DI);

        dim3 g4(DM/128, MROWS/128);
        gemm_tc<2><<<g4, 256, SMEM_BYTES>>>(p_yg, DI, out_w + (size_t)i*DM*DI, DI,
                                p_h, DM, DM, DI, 0, nullptr, nullptr);
    }

    // 3) final LN on last timestep rows only, then the 2-layer head
    ln_kernel<<<BB, 256>>>(p_h, p_last, lnf_g, lnf_b, LL, LL-1);
    head1_kernel<<<BB, 512>>>(op1_w, op1_b);
    head2_kernel<<<BB, 128>>>(op2_w, op2_b, outp);
}

// round 6
// speedup vs baseline: 1.0363x; 1.0363x over previous
#include <cuda_runtime.h>
#include <cuda_bf16.h>
#include <math.h>
#include <stdint.h>

#define BB 32
#define LL 100
#define CC 142
#define DM 512
#define DI 1024
#define NS 16
#define DTR 32
#define NL 6
#define OD 128
#define MROWS (BB*LL)
#define CPAD 160
#define SROWC 20

__device__ __align__(16) float g_h   [MROWS*DM];
__device__ __align__(16) float g_hn  [MROWS*DM];
__device__ __align__(16) float g_xz  [MROWS*2*DI];
__device__ __align__(16) float g_xc  [MROWS*DI];
__device__ __align__(16) float g_xd  [MROWS*64];
__device__ __align__(16) float g_xsp [4*MROWS*64];
__device__ __align__(16) float g_osp [2*MROWS*DM];
__device__ __align__(16) float g_dt  [MROWS*DI];
__device__ __align__(16) float g_yg  [MROWS*DI];
__device__ __align__(16) float g_xpad[MROWS*CPAD];
__device__ __align__(16) float g_wpad[DM*CPAD];
__device__ __align__(16) float g_last[BB*DM];
__device__ __align__(16) float g_hid [BB*DM];

__global__ void pad_kernel(const float* __restrict__ x, const float* __restrict__ w)
{
    int i = blockIdx.x * 256 + threadIdx.x;
    if (i < MROWS*CPAD) {
        int m = i / CPAD, c = i % CPAD;
        g_xpad[i] = (c < CC) ? x[m*CC + c] : 0.f;
    }
    int j = i - MROWS*CPAD;
    if (j >= 0 && j < DM*CPAD) {
        int m = j / CPAD, c = j % CPAD;
        g_wpad[j] = (c < CC) ? w[m*CC + c] : 0.f;
    }
}

__device__ __forceinline__ void mma_tf32(float* c, const unsigned* a, const unsigned* b)
{
    asm volatile(
        "mma.sync.aligned.m16n8k8.row.col.f32.tf32.tf32.f32 "
        "{%0,%1,%2,%3}, {%4,%5,%6,%7}, {%8,%9}, {%0,%1,%2,%3};"
        : "+f"(c[0]), "+f"(c[1]), "+f"(c[2]), "+f"(c[3])
        : "r"(a[0]), "r"(a[1]), "r"(a[2]), "r"(a[3]),
          "r"(b[0]), "r"(b[1]));
}
__device__ __forceinline__ void cp16(unsigned dst, const float* src) {
    asm volatile("cp.async.cg.shared.global [%0], [%1], 16;\n" :: "r"(dst), "l"(src));
}
__device__ __forceinline__ void cp_commit() { asm volatile("cp.async.commit_group;\n"); }
template<int N>
__device__ __forceinline__ void cp_wait() { asm volatile("cp.async.wait_group %0;\n" :: "n"(N)); }

// TF32 mma GEMM: C[M,N] = A[M,K] * W[N,K]^T (+epilogue)
// CTA tile 128 x (32*NT), 8 warps (2 x 4), warp tile 64 x (8*NT). BK=16.
// 3-stage cp.async ring, smem [rows][20] padded (conflict-free scalar LDS).
// blockIdx.z = split-K slice (A/W k-offset z*Kk, C offset z*cOff).
// EPI: 0 store, 1 +bias+pos, 2 +=, 3 softplus(+bias)
template<int NT, int EPI>
__global__ void __launch_bounds__(256) gemm_tc(
    const float* __restrict__ A, int lda,
    const float* __restrict__ W, int ldw,
    float* __restrict__ C, int ldc,
    int Kk, int cOff,
    const float* __restrict__ bias,
    const float* __restrict__ pos)
{
    constexpr int BN = 32*NT;
    constexpr int STAGE_F = (128 + BN) * SROWC;
    constexpr int BCH = (NT >= 2) ? NT/2 : 1;

    extern __shared__ __align__(16) float smem[];

    const int tid  = threadIdx.x;
    const int lane = tid & 31;
    const int wid  = tid >> 5;
    const int warp_m = wid & 1;
    const int warp_n = wid >> 1;
    const int m0 = blockIdx.y * 128;
    const int n0 = blockIdx.x * BN;
    const int zoff = blockIdx.z * Kk;

    unsigned sA[2]; const float* gA[2];
    #pragma unroll
    for (int j = 0; j < 2; j++) {
        int u = tid + j*256, r = u >> 2, kc = (u & 3)*4;
        sA[j] = (unsigned)__cvta_generic_to_shared(smem + r*SROWC + kc);
        gA[j] = A + (size_t)(m0 + r)*lda + zoff + kc;
    }
    unsigned sB[BCH]; const float* gB[BCH];
    #pragma unroll
    for (int j = 0; j < BCH; j++) {
        int u = tid + j*256, r = u >> 2, kc = (u & 3)*4;
        sB[j] = (unsigned)__cvta_generic_to_shared(smem + 128*SROWC + r*SROWC + kc);
        gB[j] = W + (size_t)(n0 + r)*ldw + zoff + kc;
    }

    const int iters = Kk >> 4;

    #pragma unroll
    for (int s = 0; s < 2; s++) {
        if (s < iters) {
            int ko = s*16;
            unsigned so = (unsigned)(s*STAGE_F*4);
            #pragma unroll
            for (int j = 0; j < 2; j++)   cp16(sA[j] + so, gA[j] + ko);
            #pragma unroll
            for (int j = 0; j < BCH; j++) cp16(sB[j] + so, gB[j] + ko);
        }
        cp_commit();
    }

    float acc[4][NT][4];
    #pragma unroll
    for (int i = 0; i < 4; i++)
        #pragma unroll
        for (int j = 0; j < NT; j++)
            #pragma unroll
            for (int r = 0; r < 4; r++) acc[i][j][r] = 0.f;

    const int lane_off = (lane >> 2)*SROWC + (lane & 3);

    int stg = 0;
    for (int it = 0; it < iters; it++) {
        cp_wait<1>();
        __syncthreads();

        {   // issue k-block it+2 (empty commit keeps group accounting aligned)
            int nit = it + 2;
            if (nit < iters) {
                int ko = nit*16;
                int ns = stg + 2; if (ns >= 3) ns -= 3;
                unsigned so = (unsigned)(ns*STAGE_F*4);
                #pragma unroll
                for (int j = 0; j < 2; j++)   cp16(sA[j] + so, gA[j] + ko);
                #pragma unroll
                for (int j = 0; j < BCH; j++) cp16(sB[j] + so, gB[j] + ko);
            }
            cp_commit();
        }

        const unsigned* as = (const unsigned*)(smem + stg*STAGE_F) + warp_m*64*SROWC + lane_off;
        const unsigned* bs = (const unsigned*)(smem + stg*STAGE_F + 128*SROWC) + warp_n*(NT*8)*SROWC + lane_off;

        #pragma unroll
        for (int ks = 0; ks < 2; ks++) {
            const int k0 = ks*8;
            unsigned afr[4][4], bfr[NT][2];
            #pragma unroll
            for (int mt = 0; mt < 4; mt++) {
                const unsigned* p = as + mt*16*SROWC + k0;
                afr[mt][0] = p[0];
                afr[mt][1] = p[8*SROWC];
                afr[mt][2] = p[4];
                afr[mt][3] = p[8*SROWC + 4];
            }
            #pragma unroll
            for (int nt = 0; nt < NT; nt++) {
                const unsigned* p = bs + nt*8*SROWC + k0;
                bfr[nt][0] = p[0];
                bfr[nt][1] = p[4];
            }
            #pragma unroll
            for (int mt = 0; mt < 4; mt++)
                #pragma unroll
                for (int nt = 0; nt < NT; nt++)
                    mma_tf32(acc[mt][nt], afr[mt], bfr[nt]);
        }

        stg++; if (stg >= 3) stg = 0;
    }

    float* Cz = C + (size_t)blockIdx.z * cOff;
    #pragma unroll
    for (int mt = 0; mt < 4; mt++) {
        #pragma unroll
        for (int rr = 0; rr < 2; rr++) {
            int r = m0 + warp_m*64 + mt*16 + (lane >> 2) + rr*8;
            #pragma unroll
            for (int nt = 0; nt < NT; nt++) {
                int c = n0 + warp_n*(NT*8) + nt*8 + (lane & 3)*2;
                float v0 = acc[mt][nt][rr*2 + 0];
                float v1 = acc[mt][nt][rr*2 + 1];
                size_t o = (size_t)r*ldc + c;
                if (EPI == 0) {
                    Cz[o]   = v0;
                    Cz[o+1] = v1;
                } else if (EPI == 1) {
                    const float* pr = pos + (size_t)(r % LL)*DM;
                    Cz[o]   = v0 + bias[c]   + pr[c];
                    Cz[o+1] = v1 + bias[c+1] + pr[c+1];
                } else if (EPI == 2) {
                    Cz[o]   += v0;
                    Cz[o+1] += v1;
                } else {
                    float u0 = v0 + bias[c];
                    float u1 = v1 + bias[c+1];
                    Cz[o]   = (u0 > 20.f) ? u0 : log1pf(__expf(u0));
                    Cz[o+1] = (u1 > 20.f) ? u1 : log1pf(__expf(u1));
                }
            }
        }
    }
}

__global__ void reduce4_kernel()
{
    int i = blockIdx.x * 256 + threadIdx.x;
    if (i < MROWS*64) {
        const int S = MROWS*64;
        g_xd[i] = (g_xsp[i] + g_xsp[i + S]) + (g_xsp[i + 2*S] + g_xsp[i + 3*S]);
    }
}

// residual add of the two out-proj split-K slices
__global__ void reduce_res_kernel()
{
    int i = blockIdx.x * 256 + threadIdx.x;
    if (i < MROWS*DM) {
        const int S = MROWS*DM;
        g_h[i] += g_osp[i] + g_osp[i + S];
    }
}

__global__ void ln_kernel(const float* __restrict__ in, float* __restrict__ out,
                          const float* __restrict__ g, const float* __restrict__ b,
                          int rowmul, int rowoff)
{
    int row = blockIdx.x * rowmul + rowoff;
    const float* x = in + (size_t)row * DM;
    int tid = threadIdx.x;
    float v0 = x[tid], v1 = x[tid + 256];
    float s = v0 + v1, sq = v0*v0 + v1*v1;
    #pragma unroll
    for (int o = 16; o; o >>= 1) {
        s  += __shfl_xor_sync(0xffffffffu, s,  o);
        sq += __shfl_xor_sync(0xffffffffu, sq, o);
    }
    __shared__ float ss[8], ssq[8];
    if ((tid & 31) == 0) { ss[tid>>5] = s; ssq[tid>>5] = sq; }
    __syncthreads();
    float ts = 0.f, tsq = 0.f;
    #pragma unroll
    for (int i = 0; i < 8; i++) { ts += ss[i]; tsq += ssq[i]; }
    float mean = ts * (1.f/DM);
    float var  = tsq * (1.f/DM) - mean*mean;
    float rs = rsqrtf(var + 1e-5f);
    size_t ob = (size_t)blockIdx.x * DM;
    out[ob + tid]       = (v0 - mean)*rs*g[tid]       + b[tid];
    out[ob + tid + 256] = (v1 - mean)*rs*g[tid + 256] + b[tid + 256];
}

__global__ void conv_kernel(const float* __restrict__ cw, const float* __restrict__ cb)
{
    int idx = blockIdx.x * 256 + threadIdx.x;
    if (idx >= MROWS*DI) return;
    int d = idx & (DI-1);
    int m = idx >> 10;
    int t = m % LL;
    float w0 = cw[d*4+0], w1 = cw[d*4+1], w2 = cw[d*4+2], w3 = cw[d*4+3];
    size_t rb = (size_t)m * (2*DI) + d;
    float acc = cb[d] + g_xz[rb] * w3;
    if (t >= 1) acc += g_xz[rb - 1*2*DI] * w2;
    if (t >= 2) acc += g_xz[rb - 2*2*DI] * w1;
    if (t >= 3) acc += g_xz[rb - 3*2*DI] * w0;
    float sig = 1.f / (1.f + __expf(-acc));
    g_xc[(size_t)m*DI + d] = acc * sig;
}

__global__ void __launch_bounds__(256) scan_kernel(const float* __restrict__ A_log,
                                                   const float* __restrict__ Dp)
{
    int b = blockIdx.y;
    int tid = threadIdx.x;
    int d = blockIdx.x * 256 + tid;
    __shared__ float sBC[2][32];

    float hs[NS], Af[NS];
    #pragma unroll
    for (int n = 0; n < NS; n++) {
        hs[n] = 0.f;
        Af[n] = -__expf(A_log[(size_t)d*NS + n]);
    }
    float base = Af[0];
    bool chain = true;
    #pragma unroll
    for (int n = 0; n < NS; n++) {
        float want = (float)(n+1) * base;
        chain = chain && (fabsf(Af[n] - want) <= 1e-4f*fabsf(want) + 1e-6f);
    }
    float Dpd = Dp[d];
    size_t bbase = (size_t)b * LL;

    if (tid < 32) sBC[0][tid] = g_xd[bbase*64 + 32 + tid];
    __syncthreads();

    for (int t = 0; t < LL; t++) {
        int cur = t & 1;
        if (t < LL-1 && tid < 32)
            sBC[cur ^ 1][tid] = g_xd[(bbase + t + 1)*64 + 32 + tid];
        size_t m = bbase + t;
        float xcv = g_xc[m*DI + d];
        float dtv = g_dt[m*DI + d];
        float zv  = g_xz[m*2*DI + DI + d];
        float dtx = dtv * xcv;
        float acc = 0.f;
        if (chain) {
            float e1 = __expf(dtv * base);
            float dA = e1;
            #pragma unroll
            for (int n = 0; n < NS; n++) {
                hs[n] = fmaf(dA, hs[n], dtx * sBC[cur][n]);
                acc = fmaf(hs[n], sBC[cur][16 + n], acc);
                dA *= e1;
            }
        } else {
            #pragma unroll
            for (int n = 0; n < NS; n++) {
                float dA = __expf(dtv * Af[n]);
                hs[n] = fmaf(dA, hs[n], dtx * sBC[cur][n]);
                acc = fmaf(hs[n], sBC[cur][16 + n], acc);
            }
        }
        float y = acc + Dpd * xcv;
        float sig = 1.f / (1.f + __expf(-zv));
        g_yg[m*DI + d] = y * (zv * sig);
        __syncthreads();
    }
}

__global__ void head1_kernel(const float* __restrict__ w, const float* __restrict__ bias)
{
    int b = blockIdx.x;
    int j = threadIdx.x;
    __shared__ float xr[DM];
    xr[j] = g_last[(size_t)b*DM + j];
    __syncthreads();
    const float4* wr = (const float4*)(w + (size_t)j*DM);
    float s = bias[j];
    #pragma unroll 4
    for (int k = 0; k < DM/4; k++) {
        float4 wv = wr[k];
        const float* xv = &xr[k*4];
        s = fmaf(wv.x, xv[0], s);
        s = fmaf(wv.y, xv[1], s);
        s = fmaf(wv.z, xv[2], s);
        s = fmaf(wv.w, xv[3], s);
    }
    g_hid[(size_t)b*DM + j] = 0.5f * s * (1.f + erff(s * 0.70710678118654752f));
}

__global__ void head2_kernel(const float* __restrict__ w, const float* __restrict__ bias,
                             float* __restrict__ out)
{
    int b = blockIdx.x;
    int o = threadIdx.x;
    __shared__ float xr[DM];
    for (int k = o; k < DM; k += 128) xr[k] = g_hid[(size_t)b*DM + k];
    __syncthreads();
    const float4* wr = (const float4*)(w + (size_t)o*DM);
    float s = bias[o];
    #pragma unroll 4
    for (int k = 0; k < DM/4; k++) {
        float4 wv = wr[k];
        const float* xv = &xr[k*4];
        s = fmaf(wv.x, xv[0], s);
        s = fmaf(wv.y, xv[1], s);
        s = fmaf(wv.z, xv[2], s);
        s = fmaf(wv.w, xv[3], s);
    }
    out[(size_t)b*OD + o] = s;
}

#define SMEMB(NT) (3*(128 + 32*(NT))*SROWC*4)

extern "C" void kernel_launch(void* const* d_in, const int* in_sizes, int n_in,
                              void* d_out, int out_size)
{
    const float* x      = (const float*)d_in[0];
    const float* inp_w  = (const float*)d_in[1];
    const float* inp_b  = (const float*)d_in[2];
    const float* pos    = (const float*)d_in[3];
    const float* norm_g = (const float*)d_in[4];
    const float* norm_b = (const float*)d_in[5];
    const float* in_w   = (const float*)d_in[6];
    const float* conv_w = (const float*)d_in[7];
    const float* conv_b = (const float*)d_in[8];
    const float* xproj_w= (const float*)d_in[9];
    const float* dt_w   = (const float*)d_in[10];
    const float* dt_b   = (const float*)d_in[11];
    const float* A_log  = (const float*)d_in[12];
    const float* Dp     = (const float*)d_in[13];
    const float* out_w  = (const float*)d_in[14];
    const float* lnf_g  = (const float*)d_in[15];
    const float* lnf_b  = (const float*)d_in[16];
    const float* op1_w  = (const float*)d_in[17];
    const float* op1_b  = (const float*)d_in[18];
    const float* op2_w  = (const float*)d_in[19];
    const float* op2_b  = (const float*)d_in[20];
    float* outp = (float*)d_out;

    float *p_h, *p_hn, *p_xz, *p_xc, *p_xd, *p_xsp, *p_osp, *p_dt, *p_yg, *p_xpad, *p_wpad, *p_last, *p_hid;
    cudaGetSymbolAddress((void**)&p_h,    g_h);
    cudaGetSymbolAddress((void**)&p_hn,   g_hn);
    cudaGetSymbolAddress((void**)&p_xz,   g_xz);
    cudaGetSymbolAddress((void**)&p_xc,   g_xc);
    cudaGetSymbolAddress((void**)&p_xd,   g_xd);
    cudaGetSymbolAddress((void**)&p_xsp,  g_xsp);
    cudaGetSymbolAddress((void**)&p_osp,  g_osp);
    cudaGetSymbolAddress((void**)&p_dt,   g_dt);
    cudaGetSymbolAddress((void**)&p_yg,   g_yg);
    cudaGetSymbolAddress((void**)&p_xpad, g_xpad);
    cudaGetSymbolAddress((void**)&p_wpad, g_wpad);
    cudaGetSymbolAddress((void**)&p_last, g_last);
    cudaGetSymbolAddress((void**)&p_hid,  g_hid);

    cudaFuncSetAttribute(gemm_tc<8,0>, cudaFuncAttributeMaxDynamicSharedMemorySize, SMEMB(8));
    cudaFuncSetAttribute(gemm_tc<4,0>, cudaFuncAttributeMaxDynamicSharedMemorySize, SMEMB(4));
    cudaFuncSetAttribute(gemm_tc<4,1>, cudaFuncAttributeMaxDynamicSharedMemorySize, SMEMB(4));
    cudaFuncSetAttribute(gemm_tc<4,3>, cudaFuncAttributeMaxDynamicSharedMemorySize, SMEMB(4));
    cudaFuncSetAttribute(gemm_tc<2,0>, cudaFuncAttributeMaxDynamicSharedMemorySize, SMEMB(2));

    // 1) embed GEMM (+bias +pos), K=144 (padded buffers stride 160)
    {
        int total = MROWS*CPAD + DM*CPAD;
        pad_kernel<<<(total + 255)/256, 256>>>(x, inp_w);
        dim3 g(DM/128, MROWS/128);
        gemm_tc<4,1><<<g, 256, SMEMB(4)>>>(p_xpad, CPAD, p_wpad, CPAD, p_h, DM, 144, 0, inp_b, pos);
    }

    // 2) layers
    for (int i = 0; i < NL; i++) {
        ln_kernel<<<MROWS, 256>>>(p_h, p_hn, norm_g + i*DM, norm_b + i*DM, 1, 0);

        // in-proj: CTA tile 128x256 (NT=8)
        dim3 g1(2*DI/256, MROWS/128);
        gemm_tc<8,0><<<g1, 256, SMEMB(8)>>>(p_hn, DM, in_w + (size_t)i*2*DI*DM, DM,
                                            p_xz, 2*DI, DM, 0, nullptr, nullptr);

        conv_kernel<<<(MROWS*DI + 255)/256, 256>>>(conv_w + (size_t)i*DI*4, conv_b + (size_t)i*DI);

        // xproj: N=64 (NT=2), split-K x4
        dim3 g2(1, MROWS/128, 4);
        gemm_tc<2,0><<<g2, 256, SMEMB(2)>>>(p_xc, DI, xproj_w + (size_t)i*64*DI, DI,
                                            p_xsp, 64, DI/4, MROWS*64, nullptr, nullptr);
        reduce4_kernel<<<(MROWS*64 + 255)/256, 256>>>();

        // dt: N=1024, K=32 (NT=4)
        dim3 g3(DI/128, MROWS/128);
        gemm_tc<4,3><<<g3, 256, SMEMB(4)>>>(p_xd, 64, dt_w + (size_t)i*DI*DTR, DTR,
                                            p_dt, DI, DTR, 0, dt_b + (size_t)i*DI, nullptr);

        dim3 gs(DI/256, BB);
        scan_kernel<<<gs, 256>>>(A_log + (size_t)i*DI*NS, Dp + (size_t)i*DI);

        // out-proj: N=512 (NT=4), split-K x2 into g_osp, then residual-reduce
        dim3 g4(DM/128, MROWS/128, 2);
        gemm_tc<4,0><<<g4, 256, SMEMB(4)>>>(p_yg, DI, out_w + (size_t)i*DM*DI, DI,
                                            p_osp, DM, DI/2, MROWS*DM, nullptr, nullptr);
        reduce_res_kernel<<<(MROWS*DM + 255)/256, 256>>>();
    }

    // 3) final LN (last timestep) + head
    ln_kernel<<<BB, 256>>>(p_h, p_last, lnf_g, lnf_b, LL, LL-1);
    head1_kernel<<<BB, 512>>>(op1_w, op1_b);
    head2_kernel<<<BB, 128>>>(op2_w, op2_b, outp);
}

// round 7
// speedup vs baseline: 1.2655x; 1.2212x over previous
#include <cuda_runtime.h>
#include <cuda_bf16.h>
#include <math.h>
#include <stdint.h>

#define BB 32
#define LL 100
#define CC 142
#define DM 512
#define DI 1024
#define NS 16
#define DTR 32
#define NL 6
#define OD 128
#define MROWS (BB*LL)
#define CPAD 160
#define SROWC 20

__device__ __align__(16) float g_h   [MROWS*DM];
__device__ __align__(16) float g_hn  [MROWS*DM];
__device__ __align__(16) float g_xz  [MROWS*2*DI];
__device__ __align__(16) float g_xc  [MROWS*DI];
__device__ __align__(16) float g_xd  [MROWS*64];
__device__ __align__(16) float g_xsp [4*MROWS*64];
__device__ __align__(16) float g_osp [2*MROWS*DM];
__device__ __align__(16) float g_dt  [MROWS*DI];
__device__ __align__(16) float g_yg  [MROWS*DI];
__device__ __align__(16) float g_xpad[MROWS*CPAD];
__device__ __align__(16) float g_wpad[DM*CPAD];
__device__ __align__(16) float g_last[BB*DM];
__device__ __align__(16) float g_hid [BB*DM];

__global__ void pad_kernel(const float* __restrict__ x, const float* __restrict__ w)
{
    int i = blockIdx.x * 256 + threadIdx.x;
    if (i < MROWS*CPAD) {
        int m = i / CPAD, c = i % CPAD;
        g_xpad[i] = (c < CC) ? x[m*CC + c] : 0.f;
    }
    int j = i - MROWS*CPAD;
    if (j >= 0 && j < DM*CPAD) {
        int m = j / CPAD, c = j % CPAD;
        g_wpad[j] = (c < CC) ? w[m*CC + c] : 0.f;
    }
}

__device__ __forceinline__ void mma_tf32(float* c, const unsigned* a, const unsigned* b)
{
    asm volatile(
        "mma.sync.aligned.m16n8k8.row.col.f32.tf32.tf32.f32 "
        "{%0,%1,%2,%3}, {%4,%5,%6,%7}, {%8,%9}, {%0,%1,%2,%3};"
        : "+f"(c[0]), "+f"(c[1]), "+f"(c[2]), "+f"(c[3])
        : "r"(a[0]), "r"(a[1]), "r"(a[2]), "r"(a[3]),
          "r"(b[0]), "r"(b[1]));
}
__device__ __forceinline__ void cp16(unsigned dst, const float* src) {
    asm volatile("cp.async.cg.shared.global [%0], [%1], 16;\n" :: "r"(dst), "l"(src));
}
__device__ __forceinline__ void cp_commit() { asm volatile("cp.async.commit_group;\n"); }
template<int N>
__device__ __forceinline__ void cp_wait() { asm volatile("cp.async.wait_group %0;\n" :: "n"(N)); }

// TF32 mma GEMM: C[M,N] = A[M,K] * W[N,K]^T (+epilogue)
// CTA tile 128 x (32*NT), 8 warps (2 x 4), warp tile 64 x (8*NT). BK=16.
// 3-stage cp.async ring, smem [rows][20] padded (conflict-free scalar LDS).
// blockIdx.z = split-K slice (A/W k-offset z*Kk, C offset z*cOff).
// EPI: 0 store, 1 +bias+pos, 2 +=, 3 softplus(+bias)
template<int NT, int EPI>
__global__ void __launch_bounds__(256) gemm_tc(
    const float* __restrict__ A, int lda,
    const float* __restrict__ W, int ldw,
    float* __restrict__ C, int ldc,
    int Kk, int cOff,
    const float* __restrict__ bias,
    const float* __restrict__ pos)
{
    constexpr int BN = 32*NT;
    constexpr int STAGE_F = (128 + BN) * SROWC;
    constexpr int BCH = (NT >= 2) ? NT/2 : 1;

    extern __shared__ __align__(16) float smem[];

    const int tid  = threadIdx.x;
    const int lane = tid & 31;
    const int wid  = tid >> 5;
    const int warp_m = wid & 1;
    const int warp_n = wid >> 1;
    const int m0 = blockIdx.y * 128;
    const int n0 = blockIdx.x * BN;
    const int zoff = blockIdx.z * Kk;

    unsigned sA[2]; const float* gA[2];
    #pragma unroll
    for (int j = 0; j < 2; j++) {
        int u = tid + j*256, r = u >> 2, kc = (u & 3)*4;
        sA[j] = (unsigned)__cvta_generic_to_shared(smem + r*SROWC + kc);
        gA[j] = A + (size_t)(m0 + r)*lda + zoff + kc;
    }
    unsigned sB[BCH]; const float* gB[BCH];
    #pragma unroll
    for (int j = 0; j < BCH; j++) {
        int u = tid + j*256, r = u >> 2, kc = (u & 3)*4;
        sB[j] = (unsigned)__cvta_generic_to_shared(smem + 128*SROWC + r*SROWC + kc);
        gB[j] = W + (size_t)(n0 + r)*ldw + zoff + kc;
    }

    const int iters = Kk >> 4;

    #pragma unroll
    for (int s = 0; s < 2; s++) {
        if (s < iters) {
            int ko = s*16;
            unsigned so = (unsigned)(s*STAGE_F*4);
            #pragma unroll
            for (int j = 0; j < 2; j++)   cp16(sA[j] + so, gA[j] + ko);
            #pragma unroll
            for (int j = 0; j < BCH; j++) cp16(sB[j] + so, gB[j] + ko);
        }
        cp_commit();
    }

    float acc[4][NT][4];
    #pragma unroll
    for (int i = 0; i < 4; i++)
        #pragma unroll
        for (int j = 0; j < NT; j++)
            #pragma unroll
            for (int r = 0; r < 4; r++) acc[i][j][r] = 0.f;

    const int lane_off = (lane >> 2)*SROWC + (lane & 3);

    int stg = 0;
    for (int it = 0; it < iters; it++) {
        cp_wait<1>();
        __syncthreads();

        {
            int nit = it + 2;
            if (nit < iters) {
                int ko = nit*16;
                int ns = stg + 2; if (ns >= 3) ns -= 3;
                unsigned so = (unsigned)(ns*STAGE_F*4);
                #pragma unroll
                for (int j = 0; j < 2; j++)   cp16(sA[j] + so, gA[j] + ko);
                #pragma unroll
                for (int j = 0; j < BCH; j++) cp16(sB[j] + so, gB[j] + ko);
            }
            cp_commit();
        }

        const unsigned* as = (const unsigned*)(smem + stg*STAGE_F) + warp_m*64*SROWC + lane_off;
        const unsigned* bs = (const unsigned*)(smem + stg*STAGE_F + 128*SROWC) + warp_n*(NT*8)*SROWC + lane_off;

        #pragma unroll
        for (int ks = 0; ks < 2; ks++) {
            const int k0 = ks*8;
            unsigned afr[4][4], bfr[NT][2];
            #pragma unroll
            for (int mt = 0; mt < 4; mt++) {
                const unsigned* p = as + mt*16*SROWC + k0;
                afr[mt][0] = p[0];
                afr[mt][1] = p[8*SROWC];
                afr[mt][2] = p[4];
                afr[mt][3] = p[8*SROWC + 4];
            }
            #pragma unroll
            for (int nt = 0; nt < NT; nt++) {
                const unsigned* p = bs + nt*8*SROWC + k0;
                bfr[nt][0] = p[0];
                bfr[nt][1] = p[4];
            }
            #pragma unroll
            for (int mt = 0; mt < 4; mt++)
                #pragma unroll
                for (int nt = 0; nt < NT; nt++)
                    mma_tf32(acc[mt][nt], afr[mt], bfr[nt]);
        }

        stg++; if (stg >= 3) stg = 0;
    }

    float* Cz = C + (size_t)blockIdx.z * cOff;
    #pragma unroll
    for (int mt = 0; mt < 4; mt++) {
        #pragma unroll
        for (int rr = 0; rr < 2; rr++) {
            int r = m0 + warp_m*64 + mt*16 + (lane >> 2) + rr*8;
            #pragma unroll
            for (int nt = 0; nt < NT; nt++) {
                int c = n0 + warp_n*(NT*8) + nt*8 + (lane & 3)*2;
                float v0 = acc[mt][nt][rr*2 + 0];
                float v1 = acc[mt][nt][rr*2 + 1];
                size_t o = (size_t)r*ldc + c;
                if (EPI == 0) {
                    Cz[o]   = v0;
                    Cz[o+1] = v1;
                } else if (EPI == 1) {
                    const float* pr = pos + (size_t)(r % LL)*DM;
                    Cz[o]   = v0 + bias[c]   + pr[c];
                    Cz[o+1] = v1 + bias[c+1] + pr[c+1];
                } else if (EPI == 2) {
                    Cz[o]   += v0;
                    Cz[o+1] += v1;
                } else {
                    float u0 = v0 + bias[c];
                    float u1 = v1 + bias[c+1];
                    Cz[o]   = (u0 > 20.f) ? u0 : log1pf(__expf(u0));
                    Cz[o+1] = (u1 > 20.f) ? u1 : log1pf(__expf(u1));
                }
            }
        }
    }
}

__global__ void reduce4_kernel()
{
    int i = blockIdx.x * 256 + threadIdx.x;
    if (i < MROWS*64) {
        const int S = MROWS*64;
        g_xd[i] = (g_xsp[i] + g_xsp[i + S]) + (g_xsp[i + 2*S] + g_xsp[i + 3*S]);
    }
}

__global__ void reduce_res_kernel()
{
    int i = blockIdx.x * 256 + threadIdx.x;
    if (i < MROWS*DM) {
        const int S = MROWS*DM;
        g_h[i] += g_osp[i] + g_osp[i + S];
    }
}

// plain LN: hn = LN(h) row-wise
__global__ void ln_kernel(const float* __restrict__ in, float* __restrict__ out,
                          const float* __restrict__ g, const float* __restrict__ b,
                          int rowmul, int rowoff)
{
    int row = blockIdx.x * rowmul + rowoff;
    const float* x = in + (size_t)row * DM;
    int tid = threadIdx.x;
    float v0 = x[tid], v1 = x[tid + 256];
    float s = v0 + v1, sq = v0*v0 + v1*v1;
    #pragma unroll
    for (int o = 16; o; o >>= 1) {
        s  += __shfl_xor_sync(0xffffffffu, s,  o);
        sq += __shfl_xor_sync(0xffffffffu, sq, o);
    }
    __shared__ float ss[8], ssq[8];
    if ((tid & 31) == 0) { ss[tid>>5] = s; ssq[tid>>5] = sq; }
    __syncthreads();
    float ts = 0.f, tsq = 0.f;
    #pragma unroll
    for (int i = 0; i < 8; i++) { ts += ss[i]; tsq += ssq[i]; }
    float mean = ts * (1.f/DM);
    float var  = tsq * (1.f/DM) - mean*mean;
    float rs = rsqrtf(var + 1e-5f);
    size_t ob = (size_t)blockIdx.x * DM;
    out[ob + tid]       = (v0 - mean)*rs*g[tid]       + b[tid];
    out[ob + tid + 256] = (v1 - mean)*rs*g[tid + 256] + b[tid + 256];
}

// fused: h += osp0+osp1 (out-proj split-K slices), then hn = LN(h)
__global__ void ln_res_kernel(const float* __restrict__ g, const float* __restrict__ b)
{
    int row = blockIdx.x;
    size_t ob = (size_t)row * DM;
    int tid = threadIdx.x;
    const int S = MROWS*DM;
    float v0 = g_h[ob + tid]       + g_osp[ob + tid]       + g_osp[ob + tid + S];
    float v1 = g_h[ob + tid + 256] + g_osp[ob + tid + 256] + g_osp[ob + tid + 256 + S];
    g_h[ob + tid]       = v0;
    g_h[ob + tid + 256] = v1;
    float s = v0 + v1, sq = v0*v0 + v1*v1;
    #pragma unroll
    for (int o = 16; o; o >>= 1) {
        s  += __shfl_xor_sync(0xffffffffu, s,  o);
        sq += __shfl_xor_sync(0xffffffffu, sq, o);
    }
    __shared__ float ss[8], ssq[8];
    if ((tid & 31) == 0) { ss[tid>>5] = s; ssq[tid>>5] = sq; }
    __syncthreads();
    float ts = 0.f, tsq = 0.f;
    #pragma unroll
    for (int i = 0; i < 8; i++) { ts += ss[i]; tsq += ssq[i]; }
    float mean = ts * (1.f/DM);
    float var  = tsq * (1.f/DM) - mean*mean;
    float rs = rsqrtf(var + 1e-5f);
    g_hn[ob + tid]       = (v0 - mean)*rs*g[tid]       + b[tid];
    g_hn[ob + tid + 256] = (v1 - mean)*rs*g[tid + 256] + b[tid + 256];
}

__global__ void conv_kernel(const float* __restrict__ cw, const float* __restrict__ cb)
{
    int idx = blockIdx.x * 256 + threadIdx.x;
    if (idx >= MROWS*DI) return;
    int d = idx & (DI-1);
    int m = idx >> 10;
    int t = m % LL;
    float w0 = cw[d*4+0], w1 = cw[d*4+1], w2 = cw[d*4+2], w3 = cw[d*4+3];
    size_t rb = (size_t)m * (2*DI) + d;
    float acc = cb[d] + g_xz[rb] * w3;
    if (t >= 1) acc += g_xz[rb - 1*2*DI] * w2;
    if (t >= 2) acc += g_xz[rb - 2*2*DI] * w1;
    if (t >= 3) acc += g_xz[rb - 3*2*DI] * w0;
    float sig = 1.f / (1.f + __expf(-acc));
    g_xc[(size_t)m*DI + d] = acc * sig;
}

// scan: whole B/C sequence staged in smem once; no barriers in the t-loop;
// next-step xc/dt/z prefetched to hide load latency.
__global__ void __launch_bounds__(256) scan_kernel(const float* __restrict__ A_log,
                                                   const float* __restrict__ Dp)
{
    int b = blockIdx.y;
    int tid = threadIdx.x;
    int d = blockIdx.x * 256 + tid;
    __shared__ float sB[LL*NS], sC[LL*NS];

    size_t bbase = (size_t)b * LL;
    for (int u = tid; u < LL*32; u += 256) {
        int t = u >> 5, j = u & 31;
        float v = g_xd[(bbase + t)*64 + 32 + j];
        if (j < NS) sB[t*NS + j] = v;
        else        sC[t*NS + (j - NS)] = v;
    }

    float hs[NS], Af[NS];
    #pragma unroll
    for (int n = 0; n < NS; n++) {
        hs[n] = 0.f;
        Af[n] = -__expf(A_log[(size_t)d*NS + n]);
    }
    float base = Af[0];
    bool chain = true;
    #pragma unroll
    for (int n = 0; n < NS; n++) {
        float want = (float)(n+1) * base;
        chain = chain && (fabsf(Af[n] - want) <= 1e-4f*fabsf(want) + 1e-6f);
    }
    float Dpd = Dp[d];
    __syncthreads();

    float xcv = g_xc[bbase*DI + d];
    float dtv = g_dt[bbase*DI + d];
    float zv  = g_xz[bbase*2*DI + DI + d];

    for (int t = 0; t < LL; t++) {
        float nxc = 0.f, ndt = 0.f, nz = 0.f;
        if (t + 1 < LL) {
            size_t mn = bbase + t + 1;
            nxc = g_xc[mn*DI + d];
            ndt = g_dt[mn*DI + d];
            nz  = g_xz[mn*2*DI + DI + d];
        }
        const float* Bp = &sB[t*NS];
        const float* Cp = &sC[t*NS];
        float dtx = dtv * xcv;
        float acc = 0.f;
        if (chain) {
            float e1 = __expf(dtv * base);
            float dA = e1;
            #pragma unroll
            for (int n = 0; n < NS; n++) {
                hs[n] = fmaf(dA, hs[n], dtx * Bp[n]);
                acc = fmaf(hs[n], Cp[n], acc);
                dA *= e1;
            }
        } else {
            #pragma unroll
            for (int n = 0; n < NS; n++) {
                float dA = __expf(dtv * Af[n]);
                hs[n] = fmaf(dA, hs[n], dtx * Bp[n]);
                acc = fmaf(hs[n], Cp[n], acc);
            }
        }
        float y = acc + Dpd * xcv;
        float sig = 1.f / (1.f + __expf(-zv));
        g_yg[(bbase + t)*DI + d] = y * (zv * sig);
        xcv = nxc; dtv = ndt; zv = nz;
    }
}

__global__ void head1_kernel(const float* __restrict__ w, const float* __restrict__ bias)
{
    int b = blockIdx.x;
    int j = threadIdx.x;
    __shared__ float xr[DM];
    xr[j] = g_last[(size_t)b*DM + j];
    __syncthreads();
    const float4* wr = (const float4*)(w + (size_t)j*DM);
    float s = bias[j];
    #pragma unroll 4
    for (int k = 0; k < DM/4; k++) {
        float4 wv = wr[k];
        const float* xv = &xr[k*4];
        s = fmaf(wv.x, xv[0], s);
        s = fmaf(wv.y, xv[1], s);
        s = fmaf(wv.z, xv[2], s);
        s = fmaf(wv.w, xv[3], s);
    }
    g_hid[(size_t)b*DM + j] = 0.5f * s * (1.f + erff(s * 0.70710678118654752f));
}

__global__ void head2_kernel(const float* __restrict__ w, const float* __restrict__ bias,
                             float* __restrict__ out)
{
    int b = blockIdx.x;
    int o = threadIdx.x;
    __shared__ float xr[DM];
    for (int k = o; k < DM; k += 128) xr[k] = g_hid[(size_t)b*DM + k];
    __syncthreads();
    const float4* wr = (const float4*)(w + (size_t)o*DM);
    float s = bias[o];
    #pragma unroll 4
    for (int k = 0; k < DM/4; k++) {
        float4 wv = wr[k];
        const float* xv = &xr[k*4];
        s = fmaf(wv.x, xv[0], s);
        s = fmaf(wv.y, xv[1], s);
        s = fmaf(wv.z, xv[2], s);
        s = fmaf(wv.w, xv[3], s);
    }
    out[(size_t)b*OD + o] = s;
}

#define SMEMB(NT) (3*(128 + 32*(NT))*SROWC*4)

extern "C" void kernel_launch(void* const* d_in, const int* in_sizes, int n_in,
                              void* d_out, int out_size)
{
    const float* x      = (const float*)d_in[0];
    const float* inp_w  = (const float*)d_in[1];
    const float* inp_b  = (const float*)d_in[2];
    const float* pos    = (const float*)d_in[3];
    const float* norm_g = (const float*)d_in[4];
    const float* norm_b = (const float*)d_in[5];
    const float* in_w   = (const float*)d_in[6];
    const float* conv_w = (const float*)d_in[7];
    const float* conv_b = (const float*)d_in[8];
    const float* xproj_w= (const float*)d_in[9];
    const float* dt_w   = (const float*)d_in[10];
    const float* dt_b   = (const float*)d_in[11];
    const float* A_log  = (const float*)d_in[12];
    const float* Dp     = (const float*)d_in[13];
    const float* out_w  = (const float*)d_in[14];
    const float* lnf_g  = (const float*)d_in[15];
    const float* lnf_b  = (const float*)d_in[16];
    const float* op1_w  = (const float*)d_in[17];
    const float* op1_b  = (const float*)d_in[18];
    const float* op2_w  = (const float*)d_in[19];
    const float* op2_b  = (const float*)d_in[20];
    float* outp = (float*)d_out;

    float *p_h, *p_hn, *p_xz, *p_xc, *p_xd, *p_xsp, *p_osp, *p_dt, *p_yg, *p_xpad, *p_wpad, *p_last, *p_hid;
    cudaGetSymbolAddress((void**)&p_h,    g_h);
    cudaGetSymbolAddress((void**)&p_hn,   g_hn);
    cudaGetSymbolAddress((void**)&p_xz,   g_xz);
    cudaGetSymbolAddress((void**)&p_xc,   g_xc);
    cudaGetSymbolAddress((void**)&p_xd,   g_xd);
    cudaGetSymbolAddress((void**)&p_xsp,  g_xsp);
    cudaGetSymbolAddress((void**)&p_osp,  g_osp);
    cudaGetSymbolAddress((void**)&p_dt,   g_dt);
    cudaGetSymbolAddress((void**)&p_yg,   g_yg);
    cudaGetSymbolAddress((void**)&p_xpad, g_xpad);
    cudaGetSymbolAddress((void**)&p_wpad, g_wpad);
    cudaGetSymbolAddress((void**)&p_last, g_last);
    cudaGetSymbolAddress((void**)&p_hid,  g_hid);

    cudaFuncSetAttribute(gemm_tc<4,0>, cudaFuncAttributeMaxDynamicSharedMemorySize, SMEMB(4));
    cudaFuncSetAttribute(gemm_tc<4,1>, cudaFuncAttributeMaxDynamicSharedMemorySize, SMEMB(4));
    cudaFuncSetAttribute(gemm_tc<4,3>, cudaFuncAttributeMaxDynamicSharedMemorySize, SMEMB(4));
    cudaFuncSetAttribute(gemm_tc<2,0>, cudaFuncAttributeMaxDynamicSharedMemorySize, SMEMB(2));

    // 1) embed GEMM (+bias +pos), K=144 (padded buffers stride 160)
    {
        int total = MROWS*CPAD + DM*CPAD;
        pad_kernel<<<(total + 255)/256, 256>>>(x, inp_w);
        dim3 g(DM/128, MROWS/128);
        gemm_tc<4,1><<<g, 256, SMEMB(4)>>>(p_xpad, CPAD, p_wpad, CPAD, p_h, DM, 144, 0, inp_b, pos);
    }

    // 2) layers
    for (int i = 0; i < NL; i++) {
        if (i == 0)
            ln_kernel<<<MROWS, 256>>>(p_h, p_hn, norm_g, norm_b, 1, 0);
        else
            ln_res_kernel<<<MROWS, 256>>>(norm_g + i*DM, norm_b + i*DM);

        // in-proj: CTA tile 128x128 (NT=4) — proven best concurrency point
        dim3 g1(2*DI/128, MROWS/128);
        gemm_tc<4,0><<<g1, 256, SMEMB(4)>>>(p_hn, DM, in_w + (size_t)i*2*DI*DM, DM,
                                            p_xz, 2*DI, DM, 0, nullptr, nullptr);

        conv_kernel<<<(MROWS*DI + 255)/256, 256>>>(conv_w + (size_t)i*DI*4, conv_b + (size_t)i*DI);

        // xproj: N=64 (NT=2), split-K x4
        dim3 g2(1, MROWS/128, 4);
        gemm_tc<2,0><<<g2, 256, SMEMB(2)>>>(p_xc, DI, xproj_w + (size_t)i*64*DI, DI,
                                            p_xsp, 64, DI/4, MROWS*64, nullptr, nullptr);
        reduce4_kernel<<<(MROWS*64 + 255)/256, 256>>>();

        // dt: N=1024, K=32 (NT=4), softplus epilogue
        dim3 g3(DI/128, MROWS/128);
        gemm_tc<4,3><<<g3, 256, SMEMB(4)>>>(p_xd, 64, dt_w + (size_t)i*DI*DTR, DTR,
                                            p_dt, DI, DTR, 0, dt_b + (size_t)i*DI, nullptr);

        dim3 gs(DI/256, BB);
        scan_kernel<<<gs, 256>>>(A_log + (size_t)i*DI*NS, Dp + (size_t)i*DI);

        // out-proj: N=512 (NT=4), split-K x2 into g_osp; reduced by next ln_res
        dim3 g4(DM/128, MROWS/128, 2);
        gemm_tc<4,0><<<g4, 256, SMEMB(4)>>>(p_yg, DI, out_w + (size_t)i*DM*DI, DI,
                                            p_osp, DM, DI/2, MROWS*DM, nullptr, nullptr);
    }

    // 3) fold in last layer's out-proj, final LN (last timestep) + head
    reduce_res_kernel<<<(MROWS*DM + 255)/256, 256>>>();
    ln_kernel<<<BB, 256>>>(p_h, p_last, lnf_g, lnf_b, LL, LL-1);
    head1_kernel<<<BB, 512>>>(op1_w, op1_b);
    head2_kernel<<<BB, 128>>>(op2_w, op2_b, outp);
}

// round 8
// speedup vs baseline: 1.5688x; 1.2397x over previous
#include <cuda_runtime.h>
#include <cuda_fp16.h>
#include <math.h>
#include <stdint.h>

#define BB 32
#define LL 100
#define CC 142
#define DM 512
#define DI 1024
#define NS 16
#define DTR 32
#define NL 6
#define OD 128
#define MROWS (BB*LL)
#define CPAD 160
#define SROWH 40   // smem row stride in halves (32 data + 8 pad) -> conflict-free

// fp32 state / GEMM outputs
__device__ __align__(16) float g_h   [MROWS*DM];
__device__ __align__(16) float g_xz  [MROWS*2*DI];
__device__ __align__(16) float g_xsp [4*MROWS*64];
__device__ __align__(16) float g_osp [2*MROWS*DM];
__device__ __align__(16) float g_dt  [MROWS*DI];
__device__ __align__(16) float g_last[BB*DM];
__device__ __align__(16) float g_hid [BB*DM];
// fp16 GEMM operands
__device__ __align__(16) __half h_inw  [NL*2*DI*DM];
__device__ __align__(16) __half h_outw [NL*DM*DI];
__device__ __align__(16) __half h_xprojw[NL*64*DI];
__device__ __align__(16) __half h_dtw  [NL*DI*DTR];
__device__ __align__(16) __half h_xpad [MROWS*CPAD];
__device__ __align__(16) __half h_wpad [DM*CPAD];
__device__ __align__(16) __half h_hn   [MROWS*DM];
__device__ __align__(16) __half h_xc   [MROWS*DI];
__device__ __align__(16) __half h_xd   [MROWS*64];
__device__ __align__(16) __half h_yg   [MROWS*DI];

// ---------------- fp32 -> fp16 convert (vec4) ----------------
__global__ void f2h_kernel(const float* __restrict__ src, __half* __restrict__ dst, int n4)
{
    int i = blockIdx.x * 256 + threadIdx.x;
    if (i < n4) {
        float4 v = ((const float4*)src)[i];
        __half2* d2 = (__half2*)dst;
        d2[i*2]   = __floats2half2_rn(v.x, v.y);
        d2[i*2+1] = __floats2half2_rn(v.z, v.w);
    }
}

// pad + convert embed operands (K=142 -> 160, zero tail)
__global__ void pad_kernel(const float* __restrict__ x, const float* __restrict__ w)
{
    int i = blockIdx.x * 256 + threadIdx.x;
    if (i < MROWS*CPAD) {
        int m = i / CPAD, c = i % CPAD;
        h_xpad[i] = (c < CC) ? __float2half(x[m*CC + c]) : __half(0.f);
    }
    int j = i - MROWS*CPAD;
    if (j >= 0 && j < DM*CPAD) {
        int m = j / CPAD, c = j % CPAD;
        h_wpad[j] = (c < CC) ? __float2half(w[m*CC + c]) : __half(0.f);
    }
}

__device__ __forceinline__ void mma_f16(float* c, const unsigned* a, const unsigned* b)
{
    asm volatile(
        "mma.sync.aligned.m16n8k16.row.col.f32.f16.f16.f32 "
        "{%0,%1,%2,%3}, {%4,%5,%6,%7}, {%8,%9}, {%0,%1,%2,%3};"
        : "+f"(c[0]), "+f"(c[1]), "+f"(c[2]), "+f"(c[3])
        : "r"(a[0]), "r"(a[1]), "r"(a[2]), "r"(a[3]),
          "r"(b[0]), "r"(b[1]));
}
__device__ __forceinline__ void cp16(unsigned dst, const __half* src) {
    asm volatile("cp.async.cg.shared.global [%0], [%1], 16;\n" :: "r"(dst), "l"(src));
}
__device__ __forceinline__ void cp_commit() { asm volatile("cp.async.commit_group;\n"); }
template<int N>
__device__ __forceinline__ void cp_wait() { asm volatile("cp.async.wait_group %0;\n" :: "n"(N)); }

// FP16 mma GEMM: C[M,N](fp32) = A[M,K](h) * W[N,K](h)^T (+epilogue)
// CTA tile 128 x (32*NT), 8 warps (2x4), warp tile 64 x (8*NT). BK=32 halves.
// 3-stage cp.async ring, smem rows [.. ][SROWH] (conflict-free LDS.32).
// blockIdx.z = split-K slice (k-offset z*Kk halves, C offset z*cOff).
// EPI: 0 store, 1 +bias+pos, 2 +=, 3 softplus(+bias)
template<int NT, int EPI>
__global__ void __launch_bounds__(256) gemm_h(
    const __half* __restrict__ A, int lda,
    const __half* __restrict__ W, int ldw,
    float* __restrict__ C, int ldc,
    int Kk, int cOff,
    const float* __restrict__ bias,
    const float* __restrict__ pos)
{
    constexpr int BN = 32*NT;
    constexpr int STAGE_H = (128 + BN) * SROWH;   // halves per stage
    constexpr int BCH = (NT >= 2) ? NT/2 : 1;

    extern __shared__ __align__(16) __half smem[];

    const int tid  = threadIdx.x;
    const int lane = tid & 31;
    const int wid  = tid >> 5;
    const int warp_m = wid & 1;
    const int warp_n = wid >> 1;
    const int m0 = blockIdx.y * 128;
    const int n0 = blockIdx.x * BN;
    const int zoff = blockIdx.z * Kk;

    // loaders: 16B chunks; chunk u -> row u>>2, c16 = (u&3)*8 halves
    unsigned sA[2]; const __half* gA[2];
    #pragma unroll
    for (int j = 0; j < 2; j++) {
        int u = tid + j*256, r = u >> 2, kc = (u & 3)*8;
        sA[j] = (unsigned)__cvta_generic_to_shared(smem + r*SROWH + kc);
        gA[j] = A + (size_t)(m0 + r)*lda + zoff + kc;
    }
    unsigned sB[BCH]; const __half* gB[BCH];
    #pragma unroll
    for (int j = 0; j < BCH; j++) {
        int u = tid + j*256, r = u >> 2, kc = (u & 3)*8;
        sB[j] = (unsigned)__cvta_generic_to_shared(smem + 128*SROWH + r*SROWH + kc);
        gB[j] = W + (size_t)(n0 + r)*ldw + zoff + kc;
    }

    const int iters = Kk >> 5;

    #pragma unroll
    for (int s = 0; s < 2; s++) {
        if (s < iters) {
            int ko = s*32;
            unsigned so = (unsigned)(s*STAGE_H*2);
            #pragma unroll
            for (int j = 0; j < 2; j++)   cp16(sA[j] + so, gA[j] + ko);
            #pragma unroll
            for (int j = 0; j < BCH; j++) cp16(sB[j] + so, gB[j] + ko);
        }
        cp_commit();
    }

    float acc[4][NT][4];
    #pragma unroll
    for (int i = 0; i < 4; i++)
        #pragma unroll
        for (int j = 0; j < NT; j++)
            #pragma unroll
            for (int r = 0; r < 4; r++) acc[i][j][r] = 0.f;

    const int lane_off = (lane >> 2)*SROWH + (lane & 3)*2;

    int stg = 0;
    for (int it = 0; it < iters; it++) {
        cp_wait<1>();
        __syncthreads();

        {
            int nit = it + 2;
            if (nit < iters) {
                int ko = nit*32;
                int ns = stg + 2; if (ns >= 3) ns -= 3;
                unsigned so = (unsigned)(ns*STAGE_H*2);
                #pragma unroll
                for (int j = 0; j < 2; j++)   cp16(sA[j] + so, gA[j] + ko);
                #pragma unroll
                for (int j = 0; j < BCH; j++) cp16(sB[j] + so, gB[j] + ko);
            }
            cp_commit();
        }

        const __half* as = smem + stg*STAGE_H + warp_m*64*SROWH + lane_off;
        const __half* bs = smem + stg*STAGE_H + 128*SROWH + warp_n*(NT*8)*SROWH + lane_off;

        #pragma unroll
        for (int ks = 0; ks < 2; ks++) {
            const int k0 = ks*16;
            unsigned afr[4][4], bfr[NT][2];
            #pragma unroll
            for (int mt = 0; mt < 4; mt++) {
                const __half* p = as + mt*16*SROWH + k0;
                afr[mt][0] = *(const unsigned*)(p);
                afr[mt][1] = *(const unsigned*)(p + 8*SROWH);
                afr[mt][2] = *(const unsigned*)(p + 8);
                afr[mt][3] = *(const unsigned*)(p + 8*SROWH + 8);
            }
            #pragma unroll
            for (int nt = 0; nt < NT; nt++) {
                const __half* p = bs + nt*8*SROWH + k0;
                bfr[nt][0] = *(const unsigned*)(p);
                bfr[nt][1] = *(const unsigned*)(p + 8);
            }
            #pragma unroll
            for (int mt = 0; mt < 4; mt++)
                #pragma unroll
                for (int nt = 0; nt < NT; nt++)
                    mma_f16(acc[mt][nt], afr[mt], bfr[nt]);
        }

        stg++; if (stg >= 3) stg = 0;
    }

    float* Cz = C + (size_t)blockIdx.z * cOff;
    #pragma unroll
    for (int mt = 0; mt < 4; mt++) {
        #pragma unroll
        for (int rr = 0; rr < 2; rr++) {
            int r = m0 + warp_m*64 + mt*16 + (lane >> 2) + rr*8;
            #pragma unroll
            for (int nt = 0; nt < NT; nt++) {
                int c = n0 + warp_n*(NT*8) + nt*8 + (lane & 3)*2;
                float v0 = acc[mt][nt][rr*2 + 0];
                float v1 = acc[mt][nt][rr*2 + 1];
                size_t o = (size_t)r*ldc + c;
                if (EPI == 0) {
                    Cz[o]   = v0;
                    Cz[o+1] = v1;
                } else if (EPI == 1) {
                    const float* pr = pos + (size_t)(r % LL)*DM;
                    Cz[o]   = v0 + bias[c]   + pr[c];
                    Cz[o+1] = v1 + bias[c+1] + pr[c+1];
                } else if (EPI == 2) {
                    Cz[o]   += v0;
                    Cz[o+1] += v1;
                } else {
                    float u0 = v0 + bias[c];
                    float u1 = v1 + bias[c+1];
                    Cz[o]   = (u0 > 20.f) ? u0 : log1pf(__expf(u0));
                    Cz[o+1] = (u1 > 20.f) ? u1 : log1pf(__expf(u1));
                }
            }
        }
    }
}

// reduce 4 xproj split-K slices -> h_xd (half)
__global__ void reduce4_kernel()
{
    int i = blockIdx.x * 256 + threadIdx.x;
    if (i < MROWS*64) {
        const int S = MROWS*64;
        h_xd[i] = __float2half((g_xsp[i] + g_xsp[i + S]) + (g_xsp[i + 2*S] + g_xsp[i + 3*S]));
    }
}

__global__ void reduce_res_kernel()
{
    int i = blockIdx.x * 256 + threadIdx.x;
    if (i < MROWS*DM) {
        const int S = MROWS*DM;
        g_h[i] += g_osp[i] + g_osp[i + S];
    }
}

// LN: hn(half) = LN(h)  (first layer)
__global__ void ln_kernel(const float* __restrict__ g, const float* __restrict__ b)
{
    int row = blockIdx.x;
    const float* x = g_h + (size_t)row * DM;
    int tid = threadIdx.x;
    float v0 = x[tid], v1 = x[tid + 256];
    float s = v0 + v1, sq = v0*v0 + v1*v1;
    #pragma unroll
    for (int o = 16; o; o >>= 1) {
        s  += __shfl_xor_sync(0xffffffffu, s,  o);
        sq += __shfl_xor_sync(0xffffffffu, sq, o);
    }
    __shared__ float ss[8], ssq[8];
    if ((tid & 31) == 0) { ss[tid>>5] = s; ssq[tid>>5] = sq; }
    __syncthreads();
    float ts = 0.f, tsq = 0.f;
    #pragma unroll
    for (int i = 0; i < 8; i++) { ts += ss[i]; tsq += ssq[i]; }
    float mean = ts * (1.f/DM);
    float var  = tsq * (1.f/DM) - mean*mean;
    float rs = rsqrtf(var + 1e-5f);
    size_t ob = (size_t)row * DM;
    h_hn[ob + tid]       = __float2half((v0 - mean)*rs*g[tid]       + b[tid]);
    h_hn[ob + tid + 256] = __float2half((v1 - mean)*rs*g[tid + 256] + b[tid + 256]);
}

// fused: h += osp0+osp1, then hn(half) = LN(h)
__global__ void ln_res_kernel(const float* __restrict__ g, const float* __restrict__ b)
{
    int row = blockIdx.x;
    size_t ob = (size_t)row * DM;
    int tid = threadIdx.x;
    const int S = MROWS*DM;
    float v0 = g_h[ob + tid]       + g_osp[ob + tid]       + g_osp[ob + tid + S];
    float v1 = g_h[ob + tid + 256] + g_osp[ob + tid + 256] + g_osp[ob + tid + 256 + S];
    g_h[ob + tid]       = v0;
    g_h[ob + tid + 256] = v1;
    float s = v0 + v1, sq = v0*v0 + v1*v1;
    #pragma unroll
    for (int o = 16; o; o >>= 1) {
        s  += __shfl_xor_sync(0xffffffffu, s,  o);
        sq += __shfl_xor_sync(0xffffffffu, sq, o);
    }
    __shared__ float ss[8], ssq[8];
    if ((tid & 31) == 0) { ss[tid>>5] = s; ssq[tid>>5] = sq; }
    __syncthreads();
    float ts = 0.f, tsq = 0.f;
    #pragma unroll
    for (int i = 0; i < 8; i++) { ts += ss[i]; tsq += ssq[i]; }
    float mean = ts * (1.f/DM);
    float var  = tsq * (1.f/DM) - mean*mean;
    float rs = rsqrtf(var + 1e-5f);
    h_hn[ob + tid]       = __float2half((v0 - mean)*rs*g[tid]       + b[tid]);
    h_hn[ob + tid + 256] = __float2half((v1 - mean)*rs*g[tid + 256] + b[tid + 256]);
}

// final LN on last timestep -> g_last (fp32)
__global__ void ln_final_kernel(const float* __restrict__ g, const float* __restrict__ b)
{
    int row = blockIdx.x * LL + (LL-1);
    const float* x = g_h + (size_t)row * DM;
    int tid = threadIdx.x;
    float v0 = x[tid], v1 = x[tid + 256];
    float s = v0 + v1, sq = v0*v0 + v1*v1;
    #pragma unroll
    for (int o = 16; o; o >>= 1) {
        s  += __shfl_xor_sync(0xffffffffu, s,  o);
        sq += __shfl_xor_sync(0xffffffffu, sq, o);
    }
    __shared__ float ss[8], ssq[8];
    if ((tid & 31) == 0) { ss[tid>>5] = s; ssq[tid>>5] = sq; }
    __syncthreads();
    float ts = 0.f, tsq = 0.f;
    #pragma unroll
    for (int i = 0; i < 8; i++) { ts += ss[i]; tsq += ssq[i]; }
    float mean = ts * (1.f/DM);
    float var  = tsq * (1.f/DM) - mean*mean;
    float rs = rsqrtf(var + 1e-5f);
    size_t ob = (size_t)blockIdx.x * DM;
    g_last[ob + tid]       = (v0 - mean)*rs*g[tid]       + b[tid];
    g_last[ob + tid + 256] = (v1 - mean)*rs*g[tid + 256] + b[tid + 256];
}

__global__ void conv_kernel(const float* __restrict__ cw, const float* __restrict__ cb)
{
    int idx = blockIdx.x * 256 + threadIdx.x;
    if (idx >= MROWS*DI) return;
    int d = idx & (DI-1);
    int m = idx >> 10;
    int t = m % LL;
    float w0 = cw[d*4+0], w1 = cw[d*4+1], w2 = cw[d*4+2], w3 = cw[d*4+3];
    size_t rb = (size_t)m * (2*DI) + d;
    float acc = cb[d] + g_xz[rb] * w3;
    if (t >= 1) acc += g_xz[rb - 1*2*DI] * w2;
    if (t >= 2) acc += g_xz[rb - 2*2*DI] * w1;
    if (t >= 3) acc += g_xz[rb - 3*2*DI] * w0;
    float sig = 1.f / (1.f + __expf(-acc));
    h_xc[(size_t)m*DI + d] = __float2half(acc * sig);
}

// scan: B/C staged in smem (from h_xd), no barriers in t-loop, prefetch next inputs
__global__ void __launch_bounds__(256) scan_kernel(const float* __restrict__ A_log,
                                                   const float* __restrict__ Dp)
{
    int b = blockIdx.y;
    int tid = threadIdx.x;
    int d = blockIdx.x * 256 + tid;
    __shared__ float sB[LL*NS], sC[LL*NS];

    size_t bbase = (size_t)b * LL;
    for (int u = tid; u < LL*32; u += 256) {
        int t = u >> 5, j = u & 31;
        float v = __half2float(h_xd[(bbase + t)*64 + 32 + j]);
        if (j < NS) sB[t*NS + j] = v;
        else        sC[t*NS + (j - NS)] = v;
    }

    float hs[NS], Af[NS];
    #pragma unroll
    for (int n = 0; n < NS; n++) {
        hs[n] = 0.f;
        Af[n] = -__expf(A_log[(size_t)d*NS + n]);
    }
    float base = Af[0];
    bool chain = true;
    #pragma unroll
    for (int n = 0; n < NS; n++) {
        float want = (float)(n+1) * base;
        chain = chain && (fabsf(Af[n] - want) <= 1e-4f*fabsf(want) + 1e-6f);
    }
    float Dpd = Dp[d];
    __syncthreads();

    float xcv = __half2float(h_xc[bbase*DI + d]);
    float dtv = g_dt[bbase*DI + d];
    float zv  = g_xz[bbase*2*DI + DI + d];

    for (int t = 0; t < LL; t++) {
        float nxc = 0.f, ndt = 0.f, nz = 0.f;
        if (t + 1 < LL) {
            size_t mn = bbase + t + 1;
            nxc = __half2float(h_xc[mn*DI + d]);
            ndt = g_dt[mn*DI + d];
            nz  = g_xz[mn*2*DI + DI + d];
        }
        const float* Bp = &sB[t*NS];
        const float* Cp = &sC[t*NS];
        float dtx = dtv * xcv;
        float acc = 0.f;
        if (chain) {
            float e1 = __expf(dtv * base);
            float dA = e1;
            #pragma unroll
            for (int n = 0; n < NS; n++) {
                hs[n] = fmaf(dA, hs[n], dtx * Bp[n]);
                acc = fmaf(hs[n], Cp[n], acc);
                dA *= e1;
            }
        } else {
            #pragma unroll
            for (int n = 0; n < NS; n++) {
                float dA = __expf(dtv * Af[n]);
                hs[n] = fmaf(dA, hs[n], dtx * Bp[n]);
                acc = fmaf(hs[n], Cp[n], acc);
            }
        }
        float y = acc + Dpd * xcv;
        float sig = 1.f / (1.f + __expf(-zv));
        h_yg[(bbase + t)*DI + d] = __float2half(y * (zv * sig));
        xcv = nxc; dtv = ndt; zv = nz;
    }
}

__global__ void head1_kernel(const float* __restrict__ w, const float* __restrict__ bias)
{
    int b = blockIdx.x;
    int j = threadIdx.x;
    __shared__ float xr[DM];
    xr[j] = g_last[(size_t)b*DM + j];
    __syncthreads();
    const float4* wr = (const float4*)(w + (size_t)j*DM);
    float s = bias[j];
    #pragma unroll 4
    for (int k = 0; k < DM/4; k++) {
        float4 wv = wr[k];
        const float* xv = &xr[k*4];
        s = fmaf(wv.x, xv[0], s);
        s = fmaf(wv.y, xv[1], s);
        s = fmaf(wv.z, xv[2], s);
        s = fmaf(wv.w, xv[3], s);
    }
    g_hid[(size_t)b*DM + j] = 0.5f * s * (1.f + erff(s * 0.70710678118654752f));
}

__global__ void head2_kernel(const float* __restrict__ w, const float* __restrict__ bias,
                             float* __restrict__ out)
{
    int b = blockIdx.x;
    int o = threadIdx.x;
    __shared__ float xr[DM];
    for (int k = o; k < DM; k += 128) xr[k] = g_hid[(size_t)b*DM + k];
    __syncthreads();
    const float4* wr = (const float4*)(w + (size_t)o*DM);
    float s = bias[o];
    #pragma unroll 4
    for (int k = 0; k < DM/4; k++) {
        float4 wv = wr[k];
        const float* xv = &xr[k*4];
        s = fmaf(wv.x, xv[0], s);
        s = fmaf(wv.y, xv[1], s);
        s = fmaf(wv.z, xv[2], s);
        s = fmaf(wv.w, xv[3], s);
    }
    out[(size_t)b*OD + o] = s;
}

#define SMEMB(NT) (3*(128 + 32*(NT))*SROWH*2)

extern "C" void kernel_launch(void* const* d_in, const int* in_sizes, int n_in,
                              void* d_out, int out_size)
{
    const float* x      = (const float*)d_in[0];
    const float* inp_w  = (const float*)d_in[1];
    const float* inp_b  = (const float*)d_in[2];
    const float* pos    = (const float*)d_in[3];
    const float* norm_g = (const float*)d_in[4];
    const float* norm_b = (const float*)d_in[5];
    const float* in_w   = (const float*)d_in[6];
    const float* conv_w = (const float*)d_in[7];
    const float* conv_b = (const float*)d_in[8];
    const float* xproj_w= (const float*)d_in[9];
    const float* dt_w   = (const float*)d_in[10];
    const float* dt_b   = (const float*)d_in[11];
    const float* A_log  = (const float*)d_in[12];
    const float* Dp     = (const float*)d_in[13];
    const float* out_w  = (const float*)d_in[14];
    const float* lnf_g  = (const float*)d_in[15];
    const float* lnf_b  = (const float*)d_in[16];
    const float* op1_w  = (const float*)d_in[17];
    const float* op1_b  = (const float*)d_in[18];
    const float* op2_w  = (const float*)d_in[19];
    const float* op2_b  = (const float*)d_in[20];
    float* outp = (float*)d_out;

    __half *ph_inw, *ph_outw, *ph_xprojw, *ph_dtw, *ph_xpad, *ph_wpad, *ph_hn, *ph_xc, *ph_xd, *ph_yg;
    cudaGetSymbolAddress((void**)&ph_inw,   h_inw);
    cudaGetSymbolAddress((void**)&ph_outw,  h_outw);
    cudaGetSymbolAddress((void**)&ph_xprojw,h_xprojw);
    cudaGetSymbolAddress((void**)&ph_dtw,   h_dtw);
    cudaGetSymbolAddress((void**)&ph_xpad,  h_xpad);
    cudaGetSymbolAddress((void**)&ph_wpad,  h_wpad);
    cudaGetSymbolAddress((void**)&ph_hn,    h_hn);
    cudaGetSymbolAddress((void**)&ph_xc,    h_xc);
    cudaGetSymbolAddress((void**)&ph_xd,    h_xd);
    cudaGetSymbolAddress((void**)&ph_yg,    h_yg);
    float *p_h, *p_xz, *p_xsp, *p_osp, *p_dt;
    cudaGetSymbolAddress((void**)&p_h,   g_h);
    cudaGetSymbolAddress((void**)&p_xz,  g_xz);
    cudaGetSymbolAddress((void**)&p_xsp, g_xsp);
    cudaGetSymbolAddress((void**)&p_osp, g_osp);
    cudaGetSymbolAddress((void**)&p_dt,  g_dt);

    cudaFuncSetAttribute(gemm_h<4,0>, cudaFuncAttributeMaxDynamicSharedMemorySize, SMEMB(4));
    cudaFuncSetAttribute(gemm_h<4,1>, cudaFuncAttributeMaxDynamicSharedMemorySize, SMEMB(4));
    cudaFuncSetAttribute(gemm_h<4,3>, cudaFuncAttributeMaxDynamicSharedMemorySize, SMEMB(4));
    cudaFuncSetAttribute(gemm_h<2,0>, cudaFuncAttributeMaxDynamicSharedMemorySize, SMEMB(2));

    // 0) weight conversion + embed pad/convert
    f2h_kernel<<<(NL*2*DI*DM/4 + 255)/256, 256>>>(in_w,    ph_inw,    NL*2*DI*DM/4);
    f2h_kernel<<<(NL*DM*DI/4   + 255)/256, 256>>>(out_w,   ph_outw,   NL*DM*DI/4);
    f2h_kernel<<<(NL*64*DI/4   + 255)/256, 256>>>(xproj_w, ph_xprojw, NL*64*DI/4);
    f2h_kernel<<<(NL*DI*DTR/4  + 255)/256, 256>>>(dt_w,    ph_dtw,    NL*DI*DTR/4);
    {
        int total = MROWS*CPAD + DM*CPAD;
        pad_kernel<<<(total + 255)/256, 256>>>(x, inp_w);
    }

    // 1) embed GEMM (+bias +pos), K=160 (zero-padded tail)
    {
        dim3 g(DM/128, MROWS/128);
        gemm_h<4,1><<<g, 256, SMEMB(4)>>>(ph_xpad, CPAD, ph_wpad, CPAD, p_h, DM, CPAD, 0, inp_b, pos);
    }

    // 2) layers
    for (int i = 0; i < NL; i++) {
        if (i == 0)
            ln_kernel<<<MROWS, 256>>>(norm_g, norm_b);
        else
            ln_res_kernel<<<MROWS, 256>>>(norm_g + i*DM, norm_b + i*DM);

        dim3 g1(2*DI/128, MROWS/128);
        gemm_h<4,0><<<g1, 256, SMEMB(4)>>>(ph_hn, DM, ph_inw + (size_t)i*2*DI*DM, DM,
                                           p_xz, 2*DI, DM, 0, nullptr, nullptr);

        conv_kernel<<<(MROWS*DI + 255)/256, 256>>>(conv_w + (size_t)i*DI*4, conv_b + (size_t)i*DI);

        dim3 g2(1, MROWS/128, 4);
        gemm_h<2,0><<<g2, 256, SMEMB(2)>>>(ph_xc, DI, ph_xprojw + (size_t)i*64*DI, DI,
                                           p_xsp, 64, DI/4, MROWS*64, nullptr, nullptr);
        reduce4_kernel<<<(MROWS*64 + 255)/256, 256>>>();

        dim3 g3(DI/128, MROWS/128);
        gemm_h<4,3><<<g3, 256, SMEMB(4)>>>(ph_xd, 64, ph_dtw + (size_t)i*DI*DTR, DTR,
                                           p_dt, DI, DTR, 0, dt_b + (size_t)i*DI, nullptr);

        dim3 gs(DI/256, BB);
        scan_kernel<<<gs, 256>>>(A_log + (size_t)i*DI*NS, Dp + (size_t)i*DI);

        dim3 g4(DM/128, MROWS/128, 2);
        gemm_h<4,0><<<g4, 256, SMEMB(4)>>>(ph_yg, DI, ph_outw + (size_t)i*DM*DI, DI,
                                           p_osp, DM, DI/2, MROWS*DM, nullptr, nullptr);
    }

    // 3) fold last out-proj, final LN (last timestep) + head
    reduce_res_kernel<<<(MROWS*DM + 255)/256, 256>>>();
    ln_final_kernel<<<BB, 256>>>(lnf_g, lnf_b);
    head1_kernel<<<BB, 512>>>(op1_w, op1_b);
    head2_kernel<<<BB, 128>>>(op2_w, op2_b, outp);
}

// round 9
// speedup vs baseline: 1.6302x; 1.0391x over previous
#include <cuda_runtime.h>
#include <cuda_fp16.h>
#include <math.h>
#include <stdint.h>

#define BB 32
#define LL 100
#define CC 142
#define DM 512
#define DI 1024
#define NS 16
#define DTR 32
#define NL 6
#define OD 128
#define MROWS (BB*LL)
#define CPAD 160
#define SROWH 40   // smem row stride in halves (32 data + 8 pad): 80B, 16B-aligned, LDSM conflict-free

// fp32 state / GEMM outputs
__device__ __align__(16) float g_h   [MROWS*DM];
__device__ __align__(16) float g_xz  [MROWS*2*DI];
__device__ __align__(16) float g_xsp [4*MROWS*64];
__device__ __align__(16) float g_osp [2*MROWS*DM];
__device__ __align__(16) float g_dt  [MROWS*DI];
__device__ __align__(16) float g_last[BB*DM];
__device__ __align__(16) float g_hid [BB*DM];
// fp16 GEMM operands
__device__ __align__(16) __half h_inw  [NL*2*DI*DM];
__device__ __align__(16) __half h_outw [NL*DM*DI];
__device__ __align__(16) __half h_xprojw[NL*64*DI];
__device__ __align__(16) __half h_dtw  [NL*DI*DTR];
__device__ __align__(16) __half h_xpad [MROWS*CPAD];
__device__ __align__(16) __half h_wpad [DM*CPAD];
__device__ __align__(16) __half h_hn   [MROWS*DM];
__device__ __align__(16) __half h_xc   [MROWS*DI];
__device__ __align__(16) __half h_xd   [MROWS*64];
__device__ __align__(16) __half h_yg   [MROWS*DI];

#define Q1 (NL*2*DI*DM/4)
#define Q2 (NL*DM*DI/4)
#define Q3 (NL*64*DI/4)
#define Q4 (NL*DI*DTR/4)

// one launch converts all four weight tensors (vec4)
__global__ void f2h_all_kernel(const float* __restrict__ in_w, const float* __restrict__ out_w,
                               const float* __restrict__ xproj_w, const float* __restrict__ dt_w)
{
    int i = blockIdx.x * 256 + threadIdx.x;
    const float* src; __half* dst; int k;
    if (i < Q1)                     { src = in_w;    dst = h_inw;    k = i; }
    else if (i < Q1+Q2)             { src = out_w;   dst = h_outw;   k = i - Q1; }
    else if (i < Q1+Q2+Q3)          { src = xproj_w; dst = h_xprojw; k = i - Q1 - Q2; }
    else if (i < Q1+Q2+Q3+Q4)       { src = dt_w;    dst = h_dtw;    k = i - Q1 - Q2 - Q3; }
    else return;
    float4 v = ((const float4*)src)[k];
    __half2* d2 = (__half2*)dst;
    d2[k*2]   = __floats2half2_rn(v.x, v.y);
    d2[k*2+1] = __floats2half2_rn(v.z, v.w);
}

// pad + convert embed operands (K=142 -> 160, zero tail)
__global__ void pad_kernel(const float* __restrict__ x, const float* __restrict__ w)
{
    int i = blockIdx.x * 256 + threadIdx.x;
    if (i < MROWS*CPAD) {
        int m = i / CPAD, c = i % CPAD;
        h_xpad[i] = (c < CC) ? __float2half(x[m*CC + c]) : __half(0.f);
    }
    int j = i - MROWS*CPAD;
    if (j >= 0 && j < DM*CPAD) {
        int m = j / CPAD, c = j % CPAD;
        h_wpad[j] = (c < CC) ? __float2half(w[m*CC + c]) : __half(0.f);
    }
}

__device__ __forceinline__ void mma_f16(float* c, const unsigned* a, const unsigned* b)
{
    asm volatile(
        "mma.sync.aligned.m16n8k16.row.col.f32.f16.f16.f32 "
        "{%0,%1,%2,%3}, {%4,%5,%6,%7}, {%8,%9}, {%0,%1,%2,%3};"
        : "+f"(c[0]), "+f"(c[1]), "+f"(c[2]), "+f"(c[3])
        : "r"(a[0]), "r"(a[1]), "r"(a[2]), "r"(a[3]),
          "r"(b[0]), "r"(b[1]));
}
#define LDSM4(r0,r1,r2,r3,addr) \
    asm volatile("ldmatrix.sync.aligned.m8n8.x4.shared.b16 {%0,%1,%2,%3}, [%4];" \
                 : "=r"(r0),"=r"(r1),"=r"(r2),"=r"(r3) : "r"(addr))
__device__ __forceinline__ void cp16(unsigned dst, const __half* src) {
    asm volatile("cp.async.cg.shared.global [%0], [%1], 16;\n" :: "r"(dst), "l"(src));
}
__device__ __forceinline__ void cp_commit() { asm volatile("cp.async.commit_group;\n"); }
template<int N>
__device__ __forceinline__ void cp_wait() { asm volatile("cp.async.wait_group %0;\n" :: "n"(N)); }

// FP16 mma GEMM with ldmatrix operand fetch.
// C[M,N](f32) = A[M,K](h) * W[N,K](h)^T (+epilogue). CTA 128 x 32*NT, 8 warps (2x4),
// warp tile 64 x 8*NT, BK=32 halves, 3-stage cp.async ring.
// blockIdx.z = split-K slice (k-offset z*Kk halves, C offset z*cOff).
// EPI: 0 store, 1 +bias+pos, 2 +=, 3 softplus(+bias)
template<int NT, int EPI>
__global__ void __launch_bounds__(256) gemm_h(
    const __half* __restrict__ A, int lda,
    const __half* __restrict__ W, int ldw,
    float* __restrict__ C, int ldc,
    int Kk, int cOff,
    const float* __restrict__ bias,
    const float* __restrict__ pos)
{
    constexpr int BN = 32*NT;
    constexpr int STAGE_H = (128 + BN) * SROWH;
    constexpr int BCH = (NT >= 2) ? NT/2 : 1;
    constexpr int NPR = NT/2;            // B ldmatrix pair count

    extern __shared__ __align__(16) __half smem[];
    const unsigned smem_u = (unsigned)__cvta_generic_to_shared(smem);

    const int tid  = threadIdx.x;
    const int lane = tid & 31;
    const int wid  = tid >> 5;
    const int warp_m = wid & 1;
    const int warp_n = wid >> 1;
    const int m0 = blockIdx.y * 128;
    const int n0 = blockIdx.x * BN;
    const int zoff = blockIdx.z * Kk;

    // cp.async loaders: 16B chunks; chunk u -> row u>>2, kc=(u&3)*8 halves
    unsigned sA[2]; const __half* gA[2];
    #pragma unroll
    for (int j = 0; j < 2; j++) {
        int u = tid + j*256, r = u >> 2, kc = (u & 3)*8;
        sA[j] = smem_u + (r*SROWH + kc)*2;
        gA[j] = A + (size_t)(m0 + r)*lda + zoff + kc;
    }
    unsigned sB[BCH]; const __half* gB[BCH];
    #pragma unroll
    for (int j = 0; j < BCH; j++) {
        int u = tid + j*256, r = u >> 2, kc = (u & 3)*8;
        sB[j] = smem_u + ((128 + r)*SROWH + kc)*2;
        gB[j] = W + (size_t)(n0 + r)*ldw + zoff + kc;
    }

    // ldmatrix per-lane offsets (bytes, relative to stage base)
    const int sub = lane >> 3, r8 = lane & 7;
    unsigned aoff[2][4];
    #pragma unroll
    for (int ks = 0; ks < 2; ks++)
        #pragma unroll
        for (int mt = 0; mt < 4; mt++) {
            int row = warp_m*64 + mt*16 + (sub & 1)*8 + r8;
            int kb  = ks*16 + (sub >> 1)*8;
            aoff[ks][mt] = (unsigned)((row*SROWH + kb)*2);
        }
    unsigned boff[2][NPR];
    #pragma unroll
    for (int ks = 0; ks < 2; ks++)
        #pragma unroll
        for (int pr = 0; pr < NPR; pr++) {
            int nt2 = sub >> 1;                 // 0: ntile pr*2, 1: ntile pr*2+1
            int kb  = ks*16 + (sub & 1)*8;
            int row = 128 + warp_n*(NT*8) + (pr*2 + nt2)*8 + r8;
            boff[ks][pr] = (unsigned)((row*SROWH + kb)*2);
        }

    const int iters = Kk >> 5;

    #pragma unroll
    for (int s = 0; s < 2; s++) {
        if (s < iters) {
            int ko = s*32;
            unsigned so = (unsigned)(s*STAGE_H*2);
            #pragma unroll
            for (int j = 0; j < 2; j++)   cp16(sA[j] + so, gA[j] + ko);
            #pragma unroll
            for (int j = 0; j < BCH; j++) cp16(sB[j] + so, gB[j] + ko);
        }
        cp_commit();
    }

    float acc[4][NT][4];
    #pragma unroll
    for (int i = 0; i < 4; i++)
        #pragma unroll
        for (int j = 0; j < NT; j++)
            #pragma unroll
            for (int r = 0; r < 4; r++) acc[i][j][r] = 0.f;

    int stg = 0;
    for (int it = 0; it < iters; it++) {
        cp_wait<1>();
        __syncthreads();

        {
            int nit = it + 2;
            if (nit < iters) {
                int ko = nit*32;
                int ns = stg + 2; if (ns >= 3) ns -= 3;
                unsigned so = (unsigned)(ns*STAGE_H*2);
                #pragma unroll
                for (int j = 0; j < 2; j++)   cp16(sA[j] + so, gA[j] + ko);
                #pragma unroll
                for (int j = 0; j < BCH; j++) cp16(sB[j] + so, gB[j] + ko);
            }
            cp_commit();
        }

        const unsigned sbase = smem_u + (unsigned)(stg*STAGE_H*2);

        #pragma unroll
        for (int ks = 0; ks < 2; ks++) {
            unsigned afr[4][4], bfr[NT][2];
            #pragma unroll
            for (int mt = 0; mt < 4; mt++)
                LDSM4(afr[mt][0], afr[mt][1], afr[mt][2], afr[mt][3], sbase + aoff[ks][mt]);
            #pragma unroll
            for (int pr = 0; pr < NPR; pr++)
                LDSM4(bfr[pr*2][0], bfr[pr*2][1], bfr[pr*2+1][0], bfr[pr*2+1][1],
                      sbase + boff[ks][pr]);
            #pragma unroll
            for (int mt = 0; mt < 4; mt++)
                #pragma unroll
                for (int nt = 0; nt < NT; nt++)
                    mma_f16(acc[mt][nt], afr[mt], bfr[nt]);
        }

        stg++; if (stg >= 3) stg = 0;
    }

    float* Cz = C + (size_t)blockIdx.z * cOff;
    #pragma unroll
    for (int mt = 0; mt < 4; mt++) {
        #pragma unroll
        for (int rr = 0; rr < 2; rr++) {
            int r = m0 + warp_m*64 + mt*16 + (lane >> 2) + rr*8;
            #pragma unroll
            for (int nt = 0; nt < NT; nt++) {
                int c = n0 + warp_n*(NT*8) + nt*8 + (lane & 3)*2;
                float v0 = acc[mt][nt][rr*2 + 0];
                float v1 = acc[mt][nt][rr*2 + 1];
                size_t o = (size_t)r*ldc + c;
                if (EPI == 0) {
                    Cz[o]   = v0;
                    Cz[o+1] = v1;
                } else if (EPI == 1) {
                    const float* pr = pos + (size_t)(r % LL)*DM;
                    Cz[o]   = v0 + bias[c]   + pr[c];
                    Cz[o+1] = v1 + bias[c+1] + pr[c+1];
                } else if (EPI == 2) {
                    Cz[o]   += v0;
                    Cz[o+1] += v1;
                } else {
                    float u0 = v0 + bias[c];
                    float u1 = v1 + bias[c+1];
                    Cz[o]   = (u0 > 20.f) ? u0 : log1pf(__expf(u0));
                    Cz[o+1] = (u1 > 20.f) ? u1 : log1pf(__expf(u1));
                }
            }
        }
    }
}

// reduce 4 xproj split-K slices -> h_xd (half)
__global__ void reduce4_kernel()
{
    int i = blockIdx.x * 256 + threadIdx.x;
    if (i < MROWS*64) {
        const int S = MROWS*64;
        h_xd[i] = __float2half((g_xsp[i] + g_xsp[i + S]) + (g_xsp[i + 2*S] + g_xsp[i + 3*S]));
    }
}

__global__ void reduce_res_kernel()
{
    int i = blockIdx.x * 256 + threadIdx.x;
    if (i < MROWS*DM) {
        const int S = MROWS*DM;
        g_h[i] += g_osp[i] + g_osp[i + S];
    }
}

// LN: hn(half) = LN(h)  (first layer)
__global__ void ln_kernel(const float* __restrict__ g, const float* __restrict__ b)
{
    int row = blockIdx.x;
    const float* x = g_h + (size_t)row * DM;
    int tid = threadIdx.x;
    float v0 = x[tid], v1 = x[tid + 256];
    float s = v0 + v1, sq = v0*v0 + v1*v1;
    #pragma unroll
    for (int o = 16; o; o >>= 1) {
        s  += __shfl_xor_sync(0xffffffffu, s,  o);
        sq += __shfl_xor_sync(0xffffffffu, sq, o);
    }
    __shared__ float ss[8], ssq[8];
    if ((tid & 31) == 0) { ss[tid>>5] = s; ssq[tid>>5] = sq; }
    __syncthreads();
    float ts = 0.f, tsq = 0.f;
    #pragma unroll
    for (int i = 0; i < 8; i++) { ts += ss[i]; tsq += ssq[i]; }
    float mean = ts * (1.f/DM);
    float var  = tsq * (1.f/DM) - mean*mean;
    float rs = rsqrtf(var + 1e-5f);
    size_t ob = (size_t)row * DM;
    h_hn[ob + tid]       = __float2half((v0 - mean)*rs*g[tid]       + b[tid]);
    h_hn[ob + tid + 256] = __float2half((v1 - mean)*rs*g[tid + 256] + b[tid + 256]);
}

// fused: h += osp0+osp1, then hn(half) = LN(h)
__global__ void ln_res_kernel(const float* __restrict__ g, const float* __restrict__ b)
{
    int row = blockIdx.x;
    size_t ob = (size_t)row * DM;
    int tid = threadIdx.x;
    const int S = MROWS*DM;
    float v0 = g_h[ob + tid]       + g_osp[ob + tid]       + g_osp[ob + tid + S];
    float v1 = g_h[ob + tid + 256] + g_osp[ob + tid + 256] + g_osp[ob + tid + 256 + S];
    g_h[ob + tid]       = v0;
    g_h[ob + tid + 256] = v1;
    float s = v0 + v1, sq = v0*v0 + v1*v1;
    #pragma unroll
    for (int o = 16; o; o >>= 1) {
        s  += __shfl_xor_sync(0xffffffffu, s,  o);
        sq += __shfl_xor_sync(0xffffffffu, sq, o);
    }
    __shared__ float ss[8], ssq[8];
    if ((tid & 31) == 0) { ss[tid>>5] = s; ssq[tid>>5] = sq; }
    __syncthreads();
    float ts = 0.f, tsq = 0.f;
    #pragma unroll
    for (int i = 0; i < 8; i++) { ts += ss[i]; tsq += ssq[i]; }
    float mean = ts * (1.f/DM);
    float var  = tsq * (1.f/DM) - mean*mean;
    float rs = rsqrtf(var + 1e-5f);
    h_hn[ob + tid]       = __float2half((v0 - mean)*rs*g[tid]       + b[tid]);
    h_hn[ob + tid + 256] = __float2half((v1 - mean)*rs*g[tid + 256] + b[tid + 256]);
}

// final LN on last timestep -> g_last (fp32)
__global__ void ln_final_kernel(const float* __restrict__ g, const float* __restrict__ b)
{
    int row = blockIdx.x * LL + (LL-1);
    const float* x = g_h + (size_t)row * DM;
    int tid = threadIdx.x;
    float v0 = x[tid], v1 = x[tid + 256];
    float s = v0 + v1, sq = v0*v0 + v1*v1;
    #pragma unroll
    for (int o = 16; o; o >>= 1) {
        s  += __shfl_xor_sync(0xffffffffu, s,  o);
        sq += __shfl_xor_sync(0xffffffffu, sq, o);
    }
    __shared__ float ss[8], ssq[8];
    if ((tid & 31) == 0) { ss[tid>>5] = s; ssq[tid>>5] = sq; }
    __syncthreads();
    float ts = 0.f, tsq = 0.f;
    #pragma unroll
    for (int i = 0; i < 8; i++) { ts += ss[i]; tsq += ssq[i]; }
    float mean = ts * (1.f/DM);
    float var  = tsq * (1.f/DM) - mean*mean;
    float rs = rsqrtf(var + 1e-5f);
    size_t ob = (size_t)blockIdx.x * DM;
    g_last[ob + tid]       = (v0 - mean)*rs*g[tid]       + b[tid];
    g_last[ob + tid + 256] = (v1 - mean)*rs*g[tid + 256] + b[tid + 256];
}

__global__ void conv_kernel(const float* __restrict__ cw, const float* __restrict__ cb)
{
    int idx = blockIdx.x * 256 + threadIdx.x;
    if (idx >= MROWS*DI) return;
    int d = idx & (DI-1);
    int m = idx >> 10;
    int t = m % LL;
    float w0 = cw[d*4+0], w1 = cw[d*4+1], w2 = cw[d*4+2], w3 = cw[d*4+3];
    size_t rb = (size_t)m * (2*DI) + d;
    float acc = cb[d] + g_xz[rb] * w3;
    if (t >= 1) acc += g_xz[rb - 1*2*DI] * w2;
    if (t >= 2) acc += g_xz[rb - 2*2*DI] * w1;
    if (t >= 3) acc += g_xz[rb - 3*2*DI] * w0;
    float sig = 1.f / (1.f + __expf(-acc));
    h_xc[(size_t)m*DI + d] = __float2half(acc * sig);
}

// scan: B/C staged in smem, no barriers in t-loop, prefetch next inputs
__global__ void __launch_bounds__(256) scan_kernel(const float* __restrict__ A_log,
                                                   const float* __restrict__ Dp)
{
    int b = blockIdx.y;
    int tid = threadIdx.x;
    int d = blockIdx.x * 256 + tid;
    __shared__ float sB[LL*NS], sC[LL*NS];

    size_t bbase = (size_t)b * LL;
    for (int u = tid; u < LL*32; u += 256) {
        int t = u >> 5, j = u & 31;
        float v = __half2float(h_xd[(bbase + t)*64 + 32 + j]);
        if (j < NS) sB[t*NS + j] = v;
        else        sC[t*NS + (j - NS)] = v;
    }

    float hs[NS], Af[NS];
    #pragma unroll
    for (int n = 0; n < NS; n++) {
        hs[n] = 0.f;
        Af[n] = -__expf(A_log[(size_t)d*NS + n]);
    }
    float base = Af[0];
    bool chain = true;
    #pragma unroll
    for (int n = 0; n < NS; n++) {
        float want = (float)(n+1) * base;
        chain = chain && (fabsf(Af[n] - want) <= 1e-4f*fabsf(want) + 1e-6f);
    }
    float Dpd = Dp[d];
    __syncthreads();

    float xcv = __half2float(h_xc[bbase*DI + d]);
    float dtv = g_dt[bbase*DI + d];
    float zv  = g_xz[bbase*2*DI + DI + d];

    for (int t = 0; t < LL; t++) {
        float nxc = 0.f, ndt = 0.f, nz = 0.f;
        if (t + 1 < LL) {
            size_t mn = bbase + t + 1;
            nxc = __half2float(h_xc[mn*DI + d]);
            ndt = g_dt[mn*DI + d];
            nz  = g_xz[mn*2*DI + DI + d];
        }
        const float* Bp = &sB[t*NS];
        const float* Cp = &sC[t*NS];
        float dtx = dtv * xcv;
        float acc = 0.f;
        if (chain) {
            float e1 = __expf(dtv * base);
            float dA = e1;
            #pragma unroll
            for (int n = 0; n < NS; n++) {
                hs[n] = fmaf(dA, hs[n], dtx * Bp[n]);
                acc = fmaf(hs[n], Cp[n], acc);
                dA *= e1;
            }
        } else {
            #pragma unroll
            for (int n = 0; n < NS; n++) {
                float dA = __expf(dtv * Af[n]);
                hs[n] = fmaf(dA, hs[n], dtx * Bp[n]);
                acc = fmaf(hs[n], Cp[n], acc);
            }
        }
        float y = acc + Dpd * xcv;
        float sig = 1.f / (1.f + __expf(-zv));
        h_yg[(bbase + t)*DI + d] = __float2half(y * (zv * sig));
        xcv = nxc; dtv = ndt; zv = nz;
    }
}

__global__ void head1_kernel(const float* __restrict__ w, const float* __restrict__ bias)
{
    int b = blockIdx.x;
    int j = threadIdx.x;
    __shared__ float xr[DM];
    xr[j] = g_last[(size_t)b*DM + j];
    __syncthreads();
    const float4* wr = (const float4*)(w + (size_t)j*DM);
    float s = bias[j];
    #pragma unroll 4
    for (int k = 0; k < DM/4; k++) {
        float4 wv = wr[k];
        const float* xv = &xr[k*4];
        s = fmaf(wv.x, xv[0], s);
        s = fmaf(wv.y, xv[1], s);
        s = fmaf(wv.z, xv[2], s);
        s = fmaf(wv.w, xv[3], s);
    }
    g_hid[(size_t)b*DM + j] = 0.5f * s * (1.f + erff(s * 0.70710678118654752f));
}

__global__ void head2_kernel(const float* __restrict__ w, const float* __restrict__ bias,
                             float* __restrict__ out)
{
    int b = blockIdx.x;
    int o = threadIdx.x;
    __shared__ float xr[DM];
    for (int k = o; k < DM; k += 128) xr[k] = g_hid[(size_t)b*DM + k];
    __syncthreads();
    const float4* wr = (const float4*)(w + (size_t)o*DM);
    float s = bias[o];
    #pragma unroll 4
    for (int k = 0; k < DM/4; k++) {
        float4 wv = wr[k];
        const float* xv = &xr[k*4];
        s = fmaf(wv.x, xv[0], s);
        s = fmaf(wv.y, xv[1], s);
        s = fmaf(wv.z, xv[2], s);
        s = fmaf(wv.w, xv[3], s);
    }
    out[(size_t)b*OD + o] = s;
}

#define SMEMB(NT) (3*(128 + 32*(NT))*SROWH*2)

extern "C" void kernel_launch(void* const* d_in, const int* in_sizes, int n_in,
                              void* d_out, int out_size)
{
    const float* x      = (const float*)d_in[0];
    const float* inp_w  = (const float*)d_in[1];
    const float* inp_b  = (const float*)d_in[2];
    const float* pos    = (const float*)d_in[3];
    const float* norm_g = (const float*)d_in[4];
    const float* norm_b = (const float*)d_in[5];
    const float* in_w   = (const float*)d_in[6];
    const float* conv_w = (const float*)d_in[7];
    const float* conv_b = (const float*)d_in[8];
    const float* xproj_w= (const float*)d_in[9];
    const float* dt_w   = (const float*)d_in[10];
    const float* dt_b   = (const float*)d_in[11];
    const float* A_log  = (const float*)d_in[12];
    const float* Dp     = (const float*)d_in[13];
    const float* out_w  = (const float*)d_in[14];
    const float* lnf_g  = (const float*)d_in[15];
    const float* lnf_b  = (const float*)d_in[16];
    const float* op1_w  = (const float*)d_in[17];
    const float* op1_b  = (const float*)d_in[18];
    const float* op2_w  = (const float*)d_in[19];
    const float* op2_b  = (const float*)d_in[20];
    float* outp = (float*)d_out;

    __half *ph_inw, *ph_outw, *ph_xprojw, *ph_dtw, *ph_xpad, *ph_wpad, *ph_hn, *ph_xc, *ph_xd, *ph_yg;
    cudaGetSymbolAddress((void**)&ph_inw,   h_inw);
    cudaGetSymbolAddress((void**)&ph_outw,  h_outw);
    cudaGetSymbolAddress((void**)&ph_xprojw,h_xprojw);
    cudaGetSymbolAddress((void**)&ph_dtw,   h_dtw);
    cudaGetSymbolAddress((void**)&ph_xpad,  h_xpad);
    cudaGetSymbolAddress((void**)&ph_wpad,  h_wpad);
    cudaGetSymbolAddress((void**)&ph_hn,    h_hn);
    cudaGetSymbolAddress((void**)&ph_xc,    h_xc);
    cudaGetSymbolAddress((void**)&ph_xd,    h_xd);
    cudaGetSymbolAddress((void**)&ph_yg,    h_yg);
    float *p_h, *p_xz, *p_xsp, *p_osp, *p_dt;
    cudaGetSymbolAddress((void**)&p_h,   g_h);
    cudaGetSymbolAddress((void**)&p_xz,  g_xz);
    cudaGetSymbolAddress((void**)&p_xsp, g_xsp);
    cudaGetSymbolAddress((void**)&p_osp, g_osp);
    cudaGetSymbolAddress((void**)&p_dt,  g_dt);

    cudaFuncSetAttribute(gemm_h<4,0>, cudaFuncAttributeMaxDynamicSharedMemorySize, SMEMB(4));
    cudaFuncSetAttribute(gemm_h<4,1>, cudaFuncAttributeMaxDynamicSharedMemorySize, SMEMB(4));
    cudaFuncSetAttribute(gemm_h<4,3>, cudaFuncAttributeMaxDynamicSharedMemorySize, SMEMB(4));
    cudaFuncSetAttribute(gemm_h<2,0>, cudaFuncAttributeMaxDynamicSharedMemorySize, SMEMB(2));

    // 0) weight conversion (one launch) + embed pad/convert
    {
        int qtot = Q1 + Q2 + Q3 + Q4;
        f2h_all_kernel<<<(qtot + 255)/256, 256>>>(in_w, out_w, xproj_w, dt_w);
        int total = MROWS*CPAD + DM*CPAD;
        pad_kernel<<<(total + 255)/256, 256>>>(x, inp_w);
    }

    // 1) embed GEMM (+bias +pos), K=160 (zero-padded tail)
    {
        dim3 g(DM/128, MROWS/128);
        gemm_h<4,1><<<g, 256, SMEMB(4)>>>(ph_xpad, CPAD, ph_wpad, CPAD, p_h, DM, CPAD, 0, inp_b, pos);
    }

    // 2) layers
    for (int i = 0; i < NL; i++) {
        if (i == 0)
            ln_kernel<<<MROWS, 256>>>(norm_g, norm_b);
        else
            ln_res_kernel<<<MROWS, 256>>>(norm_g + i*DM, norm_b + i*DM);

        dim3 g1(2*DI/128, MROWS/128);
        gemm_h<4,0><<<g1, 256, SMEMB(4)>>>(ph_hn, DM, ph_inw + (size_t)i*2*DI*DM, DM,
                                           p_xz, 2*DI, DM, 0, nullptr, nullptr);

        conv_kernel<<<(MROWS*DI + 255)/256, 256>>>(conv_w + (size_t)i*DI*4, conv_b + (size_t)i*DI);

        dim3 g2(1, MROWS/128, 4);
        gemm_h<2,0><<<g2, 256, SMEMB(2)>>>(ph_xc, DI, ph_xprojw + (size_t)i*64*DI, DI,
                                           p_xsp, 64, DI/4, MROWS*64, nullptr, nullptr);
        reduce4_kernel<<<(MROWS*64 + 255)/256, 256>>>();

        dim3 g3(DI/128, MROWS/128);
        gemm_h<4,3><<<g3, 256, SMEMB(4)>>>(ph_xd, 64, ph_dtw + (size_t)i*DI*DTR, DTR,
                                           p_dt, DI, DTR, 0, dt_b + (size_t)i*DI, nullptr);

        dim3 gs(DI/256, BB);
        scan_kernel<<<gs, 256>>>(A_log + (size_t)i*DI*NS, Dp + (size_t)i*DI);

        dim3 g4(DM/128, MROWS/128, 2);
        gemm_h<4,0><<<g4, 256, SMEMB(4)>>>(ph_yg, DI, ph_outw + (size_t)i*DM*DI, DI,
                                           p_osp, DM, DI/2, MROWS*DM, nullptr, nullptr);
    }

    // 3) fold last out-proj, final LN (last timestep) + head
    reduce_res_kernel<<<(MROWS*DM + 255)/256, 256>>>();
    ln_final_kernel<<<BB, 256>>>(lnf_g, lnf_b);
    head1_kernel<<<BB, 512>>>(op1_w, op1_b);
    head2_kernel<<<BB, 128>>>(op2_w, op2_b, outp);
}